// round 6
// baseline (speedup 1.0000x reference)
#include <cuda_runtime.h>
#include <math.h>

#define NP 36864          // 192*192 output pixels
#define WOUT 192
#define HIN 96

// ---------------- static scratch (no allocations allowed) ----------------
__device__ float g_a[64 * NP];
__device__ float g_b[256 * NP];
__device__ float g_dw[576 * NP];
__device__ float g_pw[192 * NP];
__device__ float g_mean[2 * 64 * NP];
__device__ float g_s1[2 * 64 * NP];
__device__ float g_s2[2 * 64 * NP];
__device__ float g_sigma[2 * 2 * NP];
__device__ float g_xa[2 * 64 * NP];

#define BUF_A     0
#define BUF_B     1
#define BUF_DW    2
#define BUF_PW    3
#define BUF_MEAN  4
#define BUF_S1    5
#define BUF_S2    6
#define BUF_SIGMA 7
#define BUF_XA    8

__device__ __forceinline__ float* buf_ptr(int sel) {
    switch (sel) {
        case BUF_A:     return g_a;
        case BUF_B:     return g_b;
        case BUF_DW:    return g_dw;
        case BUF_PW:    return g_pw;
        case BUF_MEAN:  return g_mean;
        case BUF_S1:    return g_s1;
        case BUF_S2:    return g_s2;
        case BUF_SIGMA: return g_sigma;
        default:        return g_xa;
    }
}

// ---------------- 1x1 conv as GEMM ----------------
// Y[oc, p] = act(bias[oc] + sum_ic W[oc*IC+ic] * X[ic*NP + p])
// BM=64, BN=128, BK=16, 256 threads, 4x8 microtile, vectorized B path.
template<int SRC, int DST, bool RELU>
__global__ void __launch_bounds__(256, 2)
k_gemm1x1(const float* __restrict__ W, const float* __restrict__ bias,
          const float* __restrict__ Xext, int IC) {
    const float* __restrict__ X = (SRC < 0) ? Xext : buf_ptr(SRC);
    float* __restrict__ Y = buf_ptr(DST);

    __shared__ float As[16][65];    // [k][m], padded
    __shared__ float Bs[16][128];   // [k][n], float4-friendly
    const int tid = threadIdx.x;
    const int tx = tid & 15, ty = tid >> 4;
    const int m0 = blockIdx.y * 64;
    const int n0 = blockIdx.x * 128;

    float acc[4][8];
#pragma unroll
    for (int i = 0; i < 4; i++)
#pragma unroll
        for (int j = 0; j < 8; j++) acc[i][j] = 0.f;

    for (int k0 = 0; k0 < IC; k0 += 16) {
        // A tile: 64x16 = 1024 elems, 4 per thread
#pragma unroll
        for (int i = 0; i < 4; i++) {
            int e = tid + i * 256;
            int k = e & 15, m = e >> 4;
            As[k][m] = (k0 + k < IC) ? W[(m0 + m) * IC + k0 + k] : 0.f;
        }
        // B tile: 16x128 = 512 float4, 2 per thread
#pragma unroll
        for (int i = 0; i < 2; i++) {
            int e = tid + i * 256;          // 0..511
            int k = e >> 5, n4 = e & 31;    // k 0..15, n4 covers 128 floats
            float4 v = make_float4(0.f, 0.f, 0.f, 0.f);
            if (k0 + k < IC)
                v = *reinterpret_cast<const float4*>(&X[(k0 + k) * NP + n0 + n4 * 4]);
            *reinterpret_cast<float4*>(&Bs[k][n4 * 4]) = v;
        }
        __syncthreads();
#pragma unroll
        for (int k = 0; k < 16; k++) {
            float a[4];
#pragma unroll
            for (int i = 0; i < 4; i++) a[i] = As[k][ty * 4 + i];
            float4 b0 = *reinterpret_cast<const float4*>(&Bs[k][tx * 8]);
            float4 b1 = *reinterpret_cast<const float4*>(&Bs[k][tx * 8 + 4]);
            float b[8] = {b0.x, b0.y, b0.z, b0.w, b1.x, b1.y, b1.z, b1.w};
#pragma unroll
            for (int i = 0; i < 4; i++)
#pragma unroll
                for (int j = 0; j < 8; j++) acc[i][j] += a[i] * b[j];
        }
        __syncthreads();
    }
#pragma unroll
    for (int i = 0; i < 4; i++) {
        int row = m0 + ty * 4 + i;
        float bb = bias[row];
        float4 o0, o1;
        float* po0 = &o0.x;
        float* po1 = &o1.x;
#pragma unroll
        for (int j = 0; j < 4; j++) {
            float v = acc[i][j] + bb;
            if (RELU) v = fmaxf(v, 0.f);
            po0[j] = v;
        }
#pragma unroll
        for (int j = 0; j < 4; j++) {
            float v = acc[i][4 + j] + bb;
            if (RELU) v = fmaxf(v, 0.f);
            po1[j] = v;
        }
        *reinterpret_cast<float4*>(&Y[row * NP + n0 + tx * 8]) = o0;
        *reinterpret_cast<float4*>(&Y[row * NP + n0 + tx * 8 + 4]) = o1;
    }
}

// ---------------- direct 3x3 conv, pad 1 ----------------
// in: (2, IC, 192, 192), out: (2, OC, 192, 192)
// 32x32 spatial tile, 2x2 pixels/thread, 16 oc per block, IC chunks of 8.
template<int SRC, int DST, bool RELU>
__global__ void __launch_bounds__(256, 2)
k_conv3x3(const float* __restrict__ W, const float* __restrict__ bias,
          int IC, int OC) {
    const float* __restrict__ in = buf_ptr(SRC);
    float* __restrict__ out = buf_ptr(DST);

    __shared__ float s_in[8][34][34];
    __shared__ float s_w[8][16][9];
    const int tx = threadIdx.x, ty = threadIdx.y;
    const int tid = ty * 16 + tx;
    const int x0 = blockIdx.x * 32, y0 = blockIdx.y * 32;
    const int noct = (OC + 15) / 16;
    const int b = blockIdx.z / noct;
    const int oc0 = (blockIdx.z % noct) * 16;

    float acc[16][2][2];
#pragma unroll
    for (int o = 0; o < 16; o++)
#pragma unroll
        for (int dy = 0; dy < 2; dy++)
#pragma unroll
            for (int dx = 0; dx < 2; dx++) acc[o][dy][dx] = 0.f;

    for (int ic0 = 0; ic0 < IC; ic0 += 8) {
        // input halo tiles: 8 x 34 x 34
        for (int ic = 0; ic < 8; ic++) {
            const float* src = in + (b * IC + ic0 + ic) * (WOUT * WOUT);
            for (int j = tid; j < 34 * 34; j += 256) {
                int yy = j / 34, xx = j - yy * 34;
                int gy = y0 + yy - 1, gx = x0 + xx - 1;
                float v = 0.f;
                if (gy >= 0 && gy < WOUT && gx >= 0 && gx < WOUT)
                    v = src[gy * WOUT + gx];
                s_in[ic][yy][xx] = v;
            }
        }
        // weights: 8 ic x 16 oc x 9
        for (int j = tid; j < 8 * 16 * 9; j += 256) {
            int o = j / 72;
            int r = j - o * 72;
            int ic = r / 9, q = r - ic * 9;
            float v = 0.f;
            if (oc0 + o < OC) v = W[((oc0 + o) * IC + ic0 + ic) * 9 + q];
            s_w[ic][o][q] = v;
        }
        __syncthreads();

        for (int ic = 0; ic < 8; ic++) {
            float v[4][4];
#pragma unroll
            for (int r = 0; r < 4; r++)
#pragma unroll
                for (int c = 0; c < 4; c++)
                    v[r][c] = s_in[ic][ty * 2 + r][tx * 2 + c];
#pragma unroll
            for (int o = 0; o < 16; o++) {
                float w[9];
#pragma unroll
                for (int q = 0; q < 9; q++) w[q] = s_w[ic][o][q];
#pragma unroll
                for (int ky = 0; ky < 3; ky++)
#pragma unroll
                    for (int kx = 0; kx < 3; kx++) {
                        float ww = w[ky * 3 + kx];
#pragma unroll
                        for (int dy = 0; dy < 2; dy++)
#pragma unroll
                            for (int dx = 0; dx < 2; dx++)
                                acc[o][dy][dx] += ww * v[dy + ky][dx + kx];
                    }
            }
        }
        __syncthreads();
    }
#pragma unroll
    for (int o = 0; o < 16; o++) {
        if (oc0 + o < OC) {
            float bb = bias[oc0 + o];
            float* dst = out + (b * OC + oc0 + o) * (WOUT * WOUT);
#pragma unroll
            for (int dy = 0; dy < 2; dy++)
#pragma unroll
                for (int dx = 0; dx < 2; dx++) {
                    float v = acc[o][dy][dx] + bb;
                    if (RELU) v = fmaxf(v, 0.f);
                    dst[(y0 + ty * 2 + dy) * WOUT + x0 + tx * 2 + dx] = v;
                }
        }
    }
}

// ---------------- gather helper ----------------
__device__ __forceinline__ void gather_h(const float* __restrict__ xbc, int iy, int ix,
                                         float* h) {
#pragma unroll
    for (int dy = 0; dy < 3; dy++)
#pragma unroll
        for (int dx = 0; dx < 3; dx++) {
            int yy = iy + dy - 1, xx = ix + dx - 1;
            h[dy * 3 + dx] =
                (yy >= 0 && yy < HIN && xx >= 0 && xx < HIN) ? xbc[yy * HIN + xx] : 0.f;
        }
}

// ---------------- gather + softmax(dw) mean ----------------
__global__ void k_mean(const float* __restrict__ x, const int* __restrict__ imY,
                       const int* __restrict__ imX) {
    int idx = blockIdx.x * blockDim.x + threadIdx.x;
    if (idx >= 2 * 64 * NP) return;
    int p = idx % NP;
    int c = (idx / NP) & 63;
    int b = idx / (64 * NP);
    int iy = imY[p], ix = imX[p];
    const float* xbc = x + (b * 64 + c) * (HIN * HIN);
    float h[9];
    gather_h(xbc, iy, ix, h);
    float d[9], mx = -1e30f;
#pragma unroll
    for (int k = 0; k < 9; k++) {
        d[k] = g_dw[(c * 9 + k) * NP + p];
        mx = fmaxf(mx, d[k]);
    }
    float s = 0.f, m = 0.f;
#pragma unroll
    for (int k = 0; k < 9; k++) {
        float e = __expf(d[k] - mx);
        s += e;
        m += h[k] * e;
    }
    g_mean[idx] = m / s;
}

// ---------------- bw + softmax + xa ----------------
__global__ void k_xa(const float* __restrict__ x, const int* __restrict__ imY,
                     const int* __restrict__ imX) {
    int idx = blockIdx.x * blockDim.x + threadIdx.x;
    if (idx >= 2 * 64 * NP) return;
    int p = idx % NP;
    int c = (idx / NP) & 63;
    int b = idx / (64 * NP);
    int iy = imY[p], ix = imX[p];
    const float* xbc = x + (b * 64 + c) * (HIN * HIN);
    float h[9];
    gather_h(xbc, iy, ix, h);
    float m = g_mean[idx];
    float sd = g_sigma[(b * 2 + 0) * NP + p];
    float sr = g_sigma[(b * 2 + 1) * NP + p];
    float bw[9], mx = -1e30f;
#pragma unroll
    for (int k = 0; k < 9; k++) {
        float d = g_dw[(c * 9 + k) * NP + p];
        bw[k] = sd * d + sr * fabsf(h[k] - m);
        mx = fmaxf(mx, bw[k]);
    }
    float s = 0.f, acc = 0.f;
#pragma unroll
    for (int k = 0; k < 9; k++) {
        float e = __expf(bw[k] - mx);
        s += e;
        acc += h[k] * e;
    }
    g_xa[idx] = acc / s;
}

// ---------------- per-pixel 64x3 contraction ----------------
__global__ void k_out(float* __restrict__ out) {
    int idx = blockIdx.x * blockDim.x + threadIdx.x;
    if (idx >= 2 * NP) return;
    int p = idx % NP, b = idx / NP;
    float a0 = 0.f, a1 = 0.f, a2 = 0.f;
#pragma unroll 8
    for (int c = 0; c < 64; c++) {
        float v = g_xa[(b * 64 + c) * NP + p];
        a0 += v * g_pw[(c * 3 + 0) * NP + p];
        a1 += v * g_pw[(c * 3 + 1) * NP + p];
        a2 += v * g_pw[(c * 3 + 2) * NP + p];
    }
    out[(b * 3 + 0) * NP + p] = a0;
    out[(b * 3 + 1) * NP + p] = a1;
    out[(b * 3 + 2) * NP + p] = a2;
}

// ---------------- launch ----------------
extern "C" void kernel_launch(void* const* d_in, const int* in_sizes, int n_in,
                              void* d_out, int out_size) {
    const float* x      = (const float*)d_in[0];
    const float* pose   = (const float*)d_in[1];
    const int*   imY    = (const int*)d_in[2];
    const int*   imX    = (const int*)d_in[3];
    const float* sig_w1 = (const float*)d_in[4];
    const float* sig_b1 = (const float*)d_in[5];
    const float* sig_w2 = (const float*)d_in[6];
    const float* sig_b2 = (const float*)d_in[7];
    const float* sig_w3 = (const float*)d_in[8];
    const float* sig_b3 = (const float*)d_in[9];
    const float* dw_w1  = (const float*)d_in[10];
    const float* dw_b1  = (const float*)d_in[11];
    const float* dw_w2  = (const float*)d_in[12];
    const float* dw_b2  = (const float*)d_in[13];
    const float* dw_w3  = (const float*)d_in[14];
    const float* dw_b3  = (const float*)d_in[15];
    const float* pw_w1  = (const float*)d_in[16];
    const float* pw_b1  = (const float*)d_in[17];
    const float* pw_w2  = (const float*)d_in[18];
    const float* pw_b2  = (const float*)d_in[19];
    const float* pw_w3  = (const float*)d_in[20];
    const float* pw_b3  = (const float*)d_in[21];

    const int NT = NP / 128;  // 288 pixel tiles (BN=128)

    // dw chain: 3 -> 64 -> 256 -> 576
    k_gemm1x1<-1, BUF_A, true ><<<dim3(NT, 1), 256>>>(dw_w1, dw_b1, pose, 3);
    k_gemm1x1<BUF_A, BUF_B, true ><<<dim3(NT, 4), 256>>>(dw_w2, dw_b2, nullptr, 64);
    k_gemm1x1<BUF_B, BUF_DW, false><<<dim3(NT, 9), 256>>>(dw_w3, dw_b3, nullptr, 256);
    // pw chain: 3 -> 64 -> 256 -> 192
    k_gemm1x1<-1, BUF_A, true ><<<dim3(NT, 1), 256>>>(pw_w1, pw_b1, pose, 3);
    k_gemm1x1<BUF_A, BUF_B, true ><<<dim3(NT, 4), 256>>>(pw_w2, pw_b2, nullptr, 64);
    k_gemm1x1<BUF_B, BUF_PW, false><<<dim3(NT, 3), 256>>>(pw_w3, pw_b3, nullptr, 256);

    // gather + softmax(dw)-weighted mean
    k_mean<<<(2 * 64 * NP) / 256, 256>>>(x, imY, imX);

    // sigma net: 3x3 convs, pad 1 (32x32 tiles)
    k_conv3x3<BUF_MEAN, BUF_S1, true ><<<dim3(6, 6, 2 * 4), dim3(16, 16)>>>(sig_w1, sig_b1, 64, 64);
    k_conv3x3<BUF_S1, BUF_S2, true ><<<dim3(6, 6, 2 * 4), dim3(16, 16)>>>(sig_w2, sig_b2, 64, 64);
    k_conv3x3<BUF_S2, BUF_SIGMA, false><<<dim3(6, 6, 2 * 1), dim3(16, 16)>>>(sig_w3, sig_b3, 64, 2);

    // bw + softmax + xa
    k_xa<<<(2 * 64 * NP) / 256, 256>>>(x, imY, imX);

    // out[b,o,p] = sum_c xa[b,c,p] * pw[c,o,p]
    k_out<<<(2 * NP + 255) / 256, 256>>>((float*)d_out);
}

// round 9
// speedup vs baseline: 1.0906x; 1.0906x over previous
#include <cuda_runtime.h>
#include <math.h>

#define NP 36864          // 192*192 output pixels
#define WOUT 192
#define HIN 96

// ---------------- static scratch (no allocations allowed) ----------------
__device__ float g_a[64 * NP];
__device__ float g_b[256 * NP];
__device__ float g_dw[576 * NP];
__device__ float g_pw[192 * NP];
__device__ float g_mean[2 * 64 * NP];
__device__ float g_s1[2 * 64 * NP];
__device__ float g_s2[2 * 64 * NP];
__device__ float g_sigma[2 * 2 * NP];
__device__ float g_xa[2 * 64 * NP];

#define BUF_A     0
#define BUF_B     1
#define BUF_DW    2
#define BUF_PW    3
#define BUF_MEAN  4
#define BUF_S1    5
#define BUF_S2    6
#define BUF_SIGMA 7
#define BUF_XA    8

__device__ __forceinline__ float* buf_ptr(int sel) {
    switch (sel) {
        case BUF_A:     return g_a;
        case BUF_B:     return g_b;
        case BUF_DW:    return g_dw;
        case BUF_PW:    return g_pw;
        case BUF_MEAN:  return g_mean;
        case BUF_S1:    return g_s1;
        case BUF_S2:    return g_s2;
        case BUF_SIGMA: return g_sigma;
        default:        return g_xa;
    }
}

// ---------------- 1x1 conv as GEMM (double-buffered) ----------------
// Y[oc, p] = act(bias[oc] + sum_ic W[oc*IC+ic] * X[ic*NP + p])
// BM=64, BN=128, BK=16, 256 threads, 4x8 microtile, float4 smem paths,
// register-staged prefetch with one __syncthreads per K-tile.
template<int SRC, int DST, bool RELU>
__global__ void __launch_bounds__(256)
k_gemm1x1(const float* __restrict__ W, const float* __restrict__ bias,
          const float* __restrict__ Xext, int IC) {
    const float* __restrict__ X = (SRC < 0) ? Xext : buf_ptr(SRC);
    float* __restrict__ Y = buf_ptr(DST);

    __shared__ float As[2][16][68];
    __shared__ float Bs[2][16][128];

    const int tid = threadIdx.x;
    const int tx = tid & 15, ty = tid >> 4;
    const int m0 = blockIdx.y * 64;
    const int n0 = blockIdx.x * 128;
    const int ntiles = (IC + 15) >> 4;

    float acc[4][8];
#pragma unroll
    for (int i = 0; i < 4; i++)
#pragma unroll
        for (int j = 0; j < 8; j++) acc[i][j] = 0.f;

    float  ra[4];
    float4 rb[2];

    // ---- prefetch tile 0 into registers ----
    {
        const int k0 = 0;
#pragma unroll
        for (int i = 0; i < 4; i++) {
            int e = tid + i * 256;
            int k = e & 15, m = e >> 4;
            ra[i] = (k0 + k < IC) ? W[(m0 + m) * IC + k0 + k] : 0.f;
        }
#pragma unroll
        for (int i = 0; i < 2; i++) {
            int e = tid + i * 256;
            int k = e >> 5, n4 = e & 31;
            rb[i] = (k0 + k < IC)
                  ? *reinterpret_cast<const float4*>(&X[(k0 + k) * NP + n0 + n4 * 4])
                  : make_float4(0.f, 0.f, 0.f, 0.f);
        }
    }
    // ---- store tile 0 ----
#pragma unroll
    for (int i = 0; i < 4; i++) {
        int e = tid + i * 256;
        As[0][e & 15][e >> 4] = ra[i];
    }
#pragma unroll
    for (int i = 0; i < 2; i++) {
        int e = tid + i * 256;
        *reinterpret_cast<float4*>(&Bs[0][e >> 5][(e & 31) * 4]) = rb[i];
    }
    __syncthreads();

    int cur = 0;
    for (int t = 0; t < ntiles; t++) {
        // prefetch next tile into registers (overlaps with compute below)
        if (t + 1 < ntiles) {
            const int k0 = (t + 1) * 16;
#pragma unroll
            for (int i = 0; i < 4; i++) {
                int e = tid + i * 256;
                int k = e & 15, m = e >> 4;
                ra[i] = (k0 + k < IC) ? W[(m0 + m) * IC + k0 + k] : 0.f;
            }
#pragma unroll
            for (int i = 0; i < 2; i++) {
                int e = tid + i * 256;
                int k = e >> 5, n4 = e & 31;
                rb[i] = (k0 + k < IC)
                      ? *reinterpret_cast<const float4*>(&X[(k0 + k) * NP + n0 + n4 * 4])
                      : make_float4(0.f, 0.f, 0.f, 0.f);
            }
        }
        // compute on current buffer
#pragma unroll
        for (int k = 0; k < 16; k++) {
            float4 av = *reinterpret_cast<const float4*>(&As[cur][k][ty * 4]);
            float4 b0 = *reinterpret_cast<const float4*>(&Bs[cur][k][tx * 8]);
            float4 b1 = *reinterpret_cast<const float4*>(&Bs[cur][k][tx * 8 + 4]);
            float a[4] = {av.x, av.y, av.z, av.w};
            float b[8] = {b0.x, b0.y, b0.z, b0.w, b1.x, b1.y, b1.z, b1.w};
#pragma unroll
            for (int i = 0; i < 4; i++)
#pragma unroll
                for (int j = 0; j < 8; j++) acc[i][j] += a[i] * b[j];
        }
        // store prefetched tile into the other buffer and flip
        if (t + 1 < ntiles) {
            int nxt = cur ^ 1;
#pragma unroll
            for (int i = 0; i < 4; i++) {
                int e = tid + i * 256;
                As[nxt][e & 15][e >> 4] = ra[i];
            }
#pragma unroll
            for (int i = 0; i < 2; i++) {
                int e = tid + i * 256;
                *reinterpret_cast<float4*>(&Bs[nxt][e >> 5][(e & 31) * 4]) = rb[i];
            }
            __syncthreads();
            cur = nxt;
        }
    }

#pragma unroll
    for (int i = 0; i < 4; i++) {
        int row = m0 + ty * 4 + i;
        float bb = bias[row];
        float4 o0, o1;
        float* po0 = &o0.x;
        float* po1 = &o1.x;
#pragma unroll
        for (int j = 0; j < 4; j++) {
            float v = acc[i][j] + bb;
            if (RELU) v = fmaxf(v, 0.f);
            po0[j] = v;
        }
#pragma unroll
        for (int j = 0; j < 4; j++) {
            float v = acc[i][4 + j] + bb;
            if (RELU) v = fmaxf(v, 0.f);
            po1[j] = v;
        }
        *reinterpret_cast<float4*>(&Y[row * NP + n0 + tx * 8]) = o0;
        *reinterpret_cast<float4*>(&Y[row * NP + n0 + tx * 8 + 4]) = o1;
    }
}

// ---------------- direct 3x3 conv, pad 1 (R3 configuration) ----------------
// in: (2, IC, 192, 192), out: (2, OC, 192, 192)
// block = 16x16 spatial tile; each block computes up to 16 output channels.
template<int SRC, int DST, bool RELU>
__global__ void k_conv3x3(const float* __restrict__ W, const float* __restrict__ bias,
                          int IC, int OC) {
    const float* __restrict__ in = buf_ptr(SRC);
    float* __restrict__ out = buf_ptr(DST);

    __shared__ float s_in[16][18][18];
    __shared__ float s_w[16][16][9];
    const int tx = threadIdx.x, ty = threadIdx.y;
    const int tid = ty * 16 + tx;
    const int x0 = blockIdx.x * 16, y0 = blockIdx.y * 16;
    const int noct = (OC + 15) / 16;
    const int b = blockIdx.z / noct;
    const int oc0 = (blockIdx.z % noct) * 16;

    float acc[16];
#pragma unroll
    for (int o = 0; o < 16; o++) acc[o] = 0.f;

    for (int ic0 = 0; ic0 < IC; ic0 += 16) {
        for (int i = tid; i < 16 * 18 * 18; i += 256) {
            int ic = i / 324;
            int r = i - ic * 324;
            int yy = r / 18, xx = r - yy * 18;
            int gy = y0 + yy - 1, gx = x0 + xx - 1;
            float v = 0.f;
            if (gy >= 0 && gy < WOUT && gx >= 0 && gx < WOUT)
                v = in[((b * IC + ic0 + ic) * WOUT + gy) * WOUT + gx];
            s_in[ic][yy][xx] = v;
        }
        for (int i = tid; i < 16 * 16 * 9; i += 256) {
            int o = i / 144;
            int r = i - o * 144;
            int ic = r / 9, j = r - ic * 9;
            float v = 0.f;
            if (oc0 + o < OC) v = W[((oc0 + o) * IC + ic0 + ic) * 9 + j];
            s_w[o][ic][j] = v;
        }
        __syncthreads();
#pragma unroll 4
        for (int ic = 0; ic < 16; ic++) {
            float v[9];
#pragma unroll
            for (int ky = 0; ky < 3; ky++)
#pragma unroll
                for (int kx = 0; kx < 3; kx++)
                    v[ky * 3 + kx] = s_in[ic][ty + ky][tx + kx];
#pragma unroll
            for (int o = 0; o < 16; o++) {
#pragma unroll
                for (int j = 0; j < 9; j++) acc[o] += s_w[o][ic][j] * v[j];
            }
        }
        __syncthreads();
    }
#pragma unroll
    for (int o = 0; o < 16; o++) {
        if (oc0 + o < OC) {
            float v = acc[o] + bias[oc0 + o];
            if (RELU) v = fmaxf(v, 0.f);
            out[((b * OC + oc0 + o) * WOUT + y0 + ty) * WOUT + x0 + tx] = v;
        }
    }
}

// ---------------- gather helper ----------------
__device__ __forceinline__ void gather_h(const float* __restrict__ xbc, int iy, int ix,
                                         float* h) {
#pragma unroll
    for (int dy = 0; dy < 3; dy++)
#pragma unroll
        for (int dx = 0; dx < 3; dx++) {
            int yy = iy + dy - 1, xx = ix + dx - 1;
            h[dy * 3 + dx] =
                (yy >= 0 && yy < HIN && xx >= 0 && xx < HIN) ? xbc[yy * HIN + xx] : 0.f;
        }
}

// ---------------- gather + softmax(dw) mean ----------------
__global__ void k_mean(const float* __restrict__ x, const int* __restrict__ imY,
                       const int* __restrict__ imX) {
    int idx = blockIdx.x * blockDim.x + threadIdx.x;
    if (idx >= 2 * 64 * NP) return;
    int p = idx % NP;
    int c = (idx / NP) & 63;
    int b = idx / (64 * NP);
    int iy = imY[p], ix = imX[p];
    const float* xbc = x + (b * 64 + c) * (HIN * HIN);
    float h[9];
    gather_h(xbc, iy, ix, h);
    float d[9], mx = -1e30f;
#pragma unroll
    for (int k = 0; k < 9; k++) {
        d[k] = g_dw[(c * 9 + k) * NP + p];
        mx = fmaxf(mx, d[k]);
    }
    float s = 0.f, m = 0.f;
#pragma unroll
    for (int k = 0; k < 9; k++) {
        float e = __expf(d[k] - mx);
        s += e;
        m += h[k] * e;
    }
    g_mean[idx] = m / s;
}

// ---------------- bw + softmax + xa ----------------
__global__ void k_xa(const float* __restrict__ x, const int* __restrict__ imY,
                     const int* __restrict__ imX) {
    int idx = blockIdx.x * blockDim.x + threadIdx.x;
    if (idx >= 2 * 64 * NP) return;
    int p = idx % NP;
    int c = (idx / NP) & 63;
    int b = idx / (64 * NP);
    int iy = imY[p], ix = imX[p];
    const float* xbc = x + (b * 64 + c) * (HIN * HIN);
    float h[9];
    gather_h(xbc, iy, ix, h);
    float m = g_mean[idx];
    float sd = g_sigma[(b * 2 + 0) * NP + p];
    float sr = g_sigma[(b * 2 + 1) * NP + p];
    float bw[9], mx = -1e30f;
#pragma unroll
    for (int k = 0; k < 9; k++) {
        float d = g_dw[(c * 9 + k) * NP + p];
        bw[k] = sd * d + sr * fabsf(h[k] - m);
        mx = fmaxf(mx, bw[k]);
    }
    float s = 0.f, acc = 0.f;
#pragma unroll
    for (int k = 0; k < 9; k++) {
        float e = __expf(bw[k] - mx);
        s += e;
        acc += h[k] * e;
    }
    g_xa[idx] = acc / s;
}

// ---------------- per-pixel 64x3 contraction ----------------
__global__ void k_out(float* __restrict__ out) {
    int idx = blockIdx.x * blockDim.x + threadIdx.x;
    if (idx >= 2 * NP) return;
    int p = idx % NP, b = idx / NP;
    float a0 = 0.f, a1 = 0.f, a2 = 0.f;
#pragma unroll 8
    for (int c = 0; c < 64; c++) {
        float v = g_xa[(b * 64 + c) * NP + p];
        a0 += v * g_pw[(c * 3 + 0) * NP + p];
        a1 += v * g_pw[(c * 3 + 1) * NP + p];
        a2 += v * g_pw[(c * 3 + 2) * NP + p];
    }
    out[(b * 3 + 0) * NP + p] = a0;
    out[(b * 3 + 1) * NP + p] = a1;
    out[(b * 3 + 2) * NP + p] = a2;
}

// ---------------- launch ----------------
extern "C" void kernel_launch(void* const* d_in, const int* in_sizes, int n_in,
                              void* d_out, int out_size) {
    const float* x      = (const float*)d_in[0];
    const float* pose   = (const float*)d_in[1];
    const int*   imY    = (const int*)d_in[2];
    const int*   imX    = (const int*)d_in[3];
    const float* sig_w1 = (const float*)d_in[4];
    const float* sig_b1 = (const float*)d_in[5];
    const float* sig_w2 = (const float*)d_in[6];
    const float* sig_b2 = (const float*)d_in[7];
    const float* sig_w3 = (const float*)d_in[8];
    const float* sig_b3 = (const float*)d_in[9];
    const float* dw_w1  = (const float*)d_in[10];
    const float* dw_b1  = (const float*)d_in[11];
    const float* dw_w2  = (const float*)d_in[12];
    const float* dw_b2  = (const float*)d_in[13];
    const float* dw_w3  = (const float*)d_in[14];
    const float* dw_b3  = (const float*)d_in[15];
    const float* pw_w1  = (const float*)d_in[16];
    const float* pw_b1  = (const float*)d_in[17];
    const float* pw_w2  = (const float*)d_in[18];
    const float* pw_b2  = (const float*)d_in[19];
    const float* pw_w3  = (const float*)d_in[20];
    const float* pw_b3  = (const float*)d_in[21];

    const int NT = NP / 128;  // 288 pixel tiles (BN=128)

    // dw chain: 3 -> 64 -> 256 -> 576
    k_gemm1x1<-1, BUF_A, true ><<<dim3(NT, 1), 256>>>(dw_w1, dw_b1, pose, 3);
    k_gemm1x1<BUF_A, BUF_B, true ><<<dim3(NT, 4), 256>>>(dw_w2, dw_b2, nullptr, 64);
    k_gemm1x1<BUF_B, BUF_DW, false><<<dim3(NT, 9), 256>>>(dw_w3, dw_b3, nullptr, 256);
    // pw chain: 3 -> 64 -> 256 -> 192
    k_gemm1x1<-1, BUF_A, true ><<<dim3(NT, 1), 256>>>(pw_w1, pw_b1, pose, 3);
    k_gemm1x1<BUF_A, BUF_B, true ><<<dim3(NT, 4), 256>>>(pw_w2, pw_b2, nullptr, 64);
    k_gemm1x1<BUF_B, BUF_PW, false><<<dim3(NT, 3), 256>>>(pw_w3, pw_b3, nullptr, 256);

    // gather + softmax(dw)-weighted mean
    k_mean<<<(2 * 64 * NP) / 256, 256>>>(x, imY, imX);

    // sigma net: 3x3 convs, pad 1 (16x16 tiles, R3 config)
    k_conv3x3<BUF_MEAN, BUF_S1, true ><<<dim3(12, 12, 2 * 4), dim3(16, 16)>>>(sig_w1, sig_b1, 64, 64);
    k_conv3x3<BUF_S1, BUF_S2, true ><<<dim3(12, 12, 2 * 4), dim3(16, 16)>>>(sig_w2, sig_b2, 64, 64);
    k_conv3x3<BUF_S2, BUF_SIGMA, false><<<dim3(12, 12, 2 * 1), dim3(16, 16)>>>(sig_w3, sig_b3, 64, 2);

    // bw + softmax + xa
    k_xa<<<(2 * 64 * NP) / 256, 256>>>(x, imY, imX);

    // out[b,o,p] = sum_c xa[b,c,p] * pw[c,o,p]
    k_out<<<(2 * NP + 255) / 256, 256>>>((float*)d_out);
}

// round 11
// speedup vs baseline: 1.6906x; 1.5502x over previous
#include <cuda_runtime.h>
#include <math.h>
#include <stdint.h>

#define NP 36864          // 192*192 output pixels
#define WOUT 192
#define HIN 96

// ---------------- static scratch (no allocations allowed) ----------------
__device__ float g_a[64 * NP];
__device__ float g_b[256 * NP];
__device__ float g_dw[576 * NP];
__device__ float g_pw[192 * NP];
__device__ float g_mean[2 * 64 * NP];
__device__ float g_s1[2 * 64 * NP];
__device__ float g_s2[2 * 64 * NP];
__device__ float g_sigma[2 * 2 * NP];
__device__ float g_xa[2 * 64 * NP];

#define BUF_A     0
#define BUF_B     1
#define BUF_DW    2
#define BUF_PW    3
#define BUF_MEAN  4
#define BUF_S1    5
#define BUF_S2    6
#define BUF_SIGMA 7
#define BUF_XA    8

__device__ __forceinline__ float* buf_ptr(int sel) {
    switch (sel) {
        case BUF_A:     return g_a;
        case BUF_B:     return g_b;
        case BUF_DW:    return g_dw;
        case BUF_PW:    return g_pw;
        case BUF_MEAN:  return g_mean;
        case BUF_S1:    return g_s1;
        case BUF_S2:    return g_s2;
        case BUF_SIGMA: return g_sigma;
        default:        return g_xa;
    }
}

// ---------------- tf32 helpers (compute_80+ portable, no tcgen05) --------
__device__ __forceinline__ float to_tf32(float x) {
    uint32_t o;
    asm("cvt.rna.tf32.f32 %0, %1;" : "=r"(o) : "f"(x));
    return __uint_as_float(o);
}
__device__ __forceinline__ void mma_tf32(float* d, const uint32_t* a, const uint32_t* b) {
    asm volatile(
        "mma.sync.aligned.m16n8k8.row.col.f32.tf32.tf32.f32 "
        "{%0,%1,%2,%3}, {%4,%5,%6,%7}, {%8,%9}, {%0,%1,%2,%3};"
        : "+f"(d[0]), "+f"(d[1]), "+f"(d[2]), "+f"(d[3])
        : "r"(a[0]), "r"(a[1]), "r"(a[2]), "r"(a[3]), "r"(b[0]), "r"(b[1]));
}

// ---------------- 1x1 conv as tf32 tensor-core GEMM ----------------
// Y[oc, p] = act(bias[oc] + sum_k W[oc*IC+k] * X[k*NP + p])
// Block tile 128(m) x 128(n), K-chunks of 32. 8 warps; warp tile 64x32
// (4 x m16 tiles, 4 x n8 tiles). Operands read directly from fp32 buffers
// and rounded to tf32 on the smem-fill path. A smem rows padded to 36
// floats and B rows to 136 floats -> conflict-free fragment loads.
template<int SRC, int DST, bool RELU>
__global__ void __launch_bounds__(256)
k_gemm_mma(const float* __restrict__ W, const float* __restrict__ bias,
           int OC, int IC) {
    const float* __restrict__ X = buf_ptr(SRC);
    float* __restrict__ Y = buf_ptr(DST);

    __shared__ __align__(16) float sA[128 * 36];   // [m][k], 36-float rows
    __shared__ __align__(16) float sB[32 * 136];   // [k][n], 136-float rows

    const int tid  = threadIdx.x;
    const int lane = tid & 31, wid = tid >> 5;
    const int m0 = blockIdx.y * 128, n0 = blockIdx.x * 128;
    const int wm = (wid & 1) * 64;     // warp m offset (2 warps in m)
    const int wn = (wid >> 1) * 32;    // warp n offset (4 warps in n)

    float acc[4][4][4];
#pragma unroll
    for (int i = 0; i < 4; i++)
#pragma unroll
        for (int j = 0; j < 4; j++)
#pragma unroll
            for (int r = 0; r < 4; r++) acc[i][j][r] = 0.f;

    const int nch = IC >> 5;
    for (int t = 0; t < nch; t++) {
        const int k0 = t * 32;
        // A tile: 128 rows x 32 k-floats = 1024 float4, 4 per thread
#pragma unroll
        for (int i = 0; i < 4; i++) {
            int e = tid + i * 256;
            int r = e >> 3, c = e & 7;
            float4 v = make_float4(0.f, 0.f, 0.f, 0.f);
            if (m0 + r < OC)
                v = *reinterpret_cast<const float4*>(W + (size_t)(m0 + r) * IC + k0 + c * 4);
            v.x = to_tf32(v.x); v.y = to_tf32(v.y);
            v.z = to_tf32(v.z); v.w = to_tf32(v.w);
            *reinterpret_cast<float4*>(sA + r * 36 + c * 4) = v;
        }
        // B tile: 32 k-rows x 128 pixels = 1024 float4, 4 per thread
#pragma unroll
        for (int i = 0; i < 4; i++) {
            int e = tid + i * 256;
            int r = e >> 5, c = e & 31;
            float4 v = *reinterpret_cast<const float4*>(X + (size_t)(k0 + r) * NP + n0 + c * 4);
            v.x = to_tf32(v.x); v.y = to_tf32(v.y);
            v.z = to_tf32(v.z); v.w = to_tf32(v.w);
            *reinterpret_cast<float4*>(sB + r * 136 + c * 4) = v;
        }
        __syncthreads();
#pragma unroll
        for (int ks = 0; ks < 4; ks++) {
            const int kk = ks * 8;
            uint32_t a[4][4], b[4][2];
#pragma unroll
            for (int i = 0; i < 4; i++) {
                const float* base = sA + (wm + i * 16 + (lane >> 2)) * 36 + kk + (lane & 3);
                a[i][0] = __float_as_uint(base[0]);
                a[i][1] = __float_as_uint(base[8 * 36]);
                a[i][2] = __float_as_uint(base[4]);
                a[i][3] = __float_as_uint(base[8 * 36 + 4]);
            }
#pragma unroll
            for (int j = 0; j < 4; j++) {
                const float* base = sB + (kk + (lane & 3)) * 136 + wn + j * 8 + (lane >> 2);
                b[j][0] = __float_as_uint(base[0]);
                b[j][1] = __float_as_uint(base[4 * 136]);
            }
#pragma unroll
            for (int i = 0; i < 4; i++)
#pragma unroll
                for (int j = 0; j < 4; j++)
                    mma_tf32(acc[i][j], a[i], b[j]);
        }
        __syncthreads();
    }

    // epilogue: d0,d1 -> row lane/4, cols (lane%4)*2,+1; d2,d3 -> row +8
#pragma unroll
    for (int i = 0; i < 4; i++) {
#pragma unroll
        for (int half = 0; half < 2; half++) {
            int oc = m0 + wm + i * 16 + (lane >> 2) + half * 8;
            if (oc < OC) {
                float bb = bias[oc];
#pragma unroll
                for (int j = 0; j < 4; j++) {
                    int col = n0 + wn + j * 8 + (lane & 3) * 2;
                    float v0 = acc[i][j][half * 2 + 0] + bb;
                    float v1 = acc[i][j][half * 2 + 1] + bb;
                    if (RELU) { v0 = fmaxf(v0, 0.f); v1 = fmaxf(v1, 0.f); }
                    *reinterpret_cast<float2*>(Y + (size_t)oc * NP + col) =
                        make_float2(v0, v1);
                }
            }
        }
    }
}

// ---------------- small fp32 GEMM for layer 1 (IC=3) ----------------
template<int SRC, int DST, bool RELU>
__global__ void k_gemm1x1(const float* __restrict__ W, const float* __restrict__ bias,
                          const float* __restrict__ Xext, int IC) {
    const float* __restrict__ X = (SRC < 0) ? Xext : buf_ptr(SRC);
    float* __restrict__ Y = buf_ptr(DST);

    __shared__ float As[16][65];
    __shared__ float Bs[16][64];
    const int tid = threadIdx.x;
    const int tx = tid & 15, ty = tid >> 4;
    const int m0 = blockIdx.y * 64;
    const int n0 = blockIdx.x * 64;

    float acc[4][4];
#pragma unroll
    for (int i = 0; i < 4; i++)
#pragma unroll
        for (int j = 0; j < 4; j++) acc[i][j] = 0.f;

    for (int k0 = 0; k0 < IC; k0 += 16) {
#pragma unroll
        for (int i = 0; i < 4; i++) {
            int e = tid + i * 256;
            int k = e & 15, m = e >> 4;
            As[k][m] = (k0 + k < IC) ? W[(m0 + m) * IC + k0 + k] : 0.f;
        }
#pragma unroll
        for (int i = 0; i < 4; i++) {
            int e = tid + i * 256;
            int n = e & 63, k = e >> 6;
            Bs[k][n] = (k0 + k < IC) ? X[(k0 + k) * NP + n0 + n] : 0.f;
        }
        __syncthreads();
#pragma unroll
        for (int k = 0; k < 16; k++) {
            float a[4], b[4];
#pragma unroll
            for (int i = 0; i < 4; i++) a[i] = As[k][ty * 4 + i];
#pragma unroll
            for (int j = 0; j < 4; j++) b[j] = Bs[k][tx * 4 + j];
#pragma unroll
            for (int i = 0; i < 4; i++)
#pragma unroll
                for (int j = 0; j < 4; j++) acc[i][j] += a[i] * b[j];
        }
        __syncthreads();
    }
#pragma unroll
    for (int i = 0; i < 4; i++) {
        float bb = bias[m0 + ty * 4 + i];
#pragma unroll
        for (int j = 0; j < 4; j++) {
            float v = acc[i][j] + bb;
            if (RELU) v = fmaxf(v, 0.f);
            Y[(m0 + ty * 4 + i) * NP + n0 + tx * 4 + j] = v;
        }
    }
}

// ---------------- direct 3x3 conv, pad 1 (1x2 pixels/thread) ----------------
// in: (2, IC, 192, 192), out: (2, OC, 192, 192)
// 16(w) x 32(h) spatial tile, each thread computes 2 vertical pixels,
// 16 oc per block, IC chunks of 8.
template<int SRC, int DST, bool RELU>
__global__ void k_conv3x3(const float* __restrict__ W, const float* __restrict__ bias,
                          int IC, int OC) {
    const float* __restrict__ in = buf_ptr(SRC);
    float* __restrict__ out = buf_ptr(DST);

    __shared__ float s_in[8][34][18];
    __shared__ float s_w[8][16][9];
    const int tx = threadIdx.x, ty = threadIdx.y;
    const int tid = ty * 16 + tx;
    const int x0 = blockIdx.x * 16, y0 = blockIdx.y * 32;
    const int noct = (OC + 15) / 16;
    const int b = blockIdx.z / noct;
    const int oc0 = (blockIdx.z % noct) * 16;

    float acc[16][2];
#pragma unroll
    for (int o = 0; o < 16; o++) { acc[o][0] = 0.f; acc[o][1] = 0.f; }

    for (int ic0 = 0; ic0 < IC; ic0 += 8) {
        for (int i = tid; i < 8 * 34 * 18; i += 256) {
            int ic = i / 612;
            int r = i - ic * 612;
            int yy = r / 18, xx = r - yy * 18;
            int gy = y0 + yy - 1, gx = x0 + xx - 1;
            float v = 0.f;
            if (gy >= 0 && gy < WOUT && gx >= 0 && gx < WOUT)
                v = in[((b * IC + ic0 + ic) * WOUT + gy) * WOUT + gx];
            s_in[ic][yy][xx] = v;
        }
        for (int i = tid; i < 8 * 16 * 9; i += 256) {
            int o = i / 72;
            int r = i - o * 72;
            int ic = r / 9, j = r - ic * 9;
            float v = 0.f;
            if (oc0 + o < OC) v = W[((oc0 + o) * IC + ic0 + ic) * 9 + j];
            s_w[ic][o][j] = v;
        }
        __syncthreads();
#pragma unroll 2
        for (int ic = 0; ic < 8; ic++) {
            float v[4][3];
#pragma unroll
            for (int r = 0; r < 4; r++)
#pragma unroll
                for (int c = 0; c < 3; c++)
                    v[r][c] = s_in[ic][ty * 2 + r][tx + c];
#pragma unroll
            for (int o = 0; o < 16; o++) {
#pragma unroll
                for (int ky = 0; ky < 3; ky++)
#pragma unroll
                    for (int kx = 0; kx < 3; kx++) {
                        float ww = s_w[ic][o][ky * 3 + kx];
                        acc[o][0] += ww * v[ky][kx];
                        acc[o][1] += ww * v[ky + 1][kx];
                    }
            }
        }
        __syncthreads();
    }
#pragma unroll
    for (int o = 0; o < 16; o++) {
        if (oc0 + o < OC) {
            float bb = bias[oc0 + o];
            float* dst = out + ((size_t)(b * OC + oc0 + o) * WOUT + y0 + ty * 2) * WOUT
                         + x0 + tx;
#pragma unroll
            for (int dy = 0; dy < 2; dy++) {
                float v = acc[o][dy] + bb;
                if (RELU) v = fmaxf(v, 0.f);
                dst[dy * WOUT] = v;
            }
        }
    }
}

// ---------------- gather helper ----------------
__device__ __forceinline__ void gather_h(const float* __restrict__ xbc, int iy, int ix,
                                         float* h) {
#pragma unroll
    for (int dy = 0; dy < 3; dy++)
#pragma unroll
        for (int dx = 0; dx < 3; dx++) {
            int yy = iy + dy - 1, xx = ix + dx - 1;
            h[dy * 3 + dx] =
                (yy >= 0 && yy < HIN && xx >= 0 && xx < HIN) ? xbc[yy * HIN + xx] : 0.f;
        }
}

// ---------------- gather + softmax(dw) mean ----------------
__global__ void k_mean(const float* __restrict__ x, const int* __restrict__ imY,
                       const int* __restrict__ imX) {
    int idx = blockIdx.x * blockDim.x + threadIdx.x;
    if (idx >= 2 * 64 * NP) return;
    int p = idx % NP;
    int c = (idx / NP) & 63;
    int b = idx / (64 * NP);
    int iy = imY[p], ix = imX[p];
    const float* xbc = x + (b * 64 + c) * (HIN * HIN);
    float h[9];
    gather_h(xbc, iy, ix, h);
    float d[9], mx = -1e30f;
#pragma unroll
    for (int k = 0; k < 9; k++) {
        d[k] = g_dw[(c * 9 + k) * NP + p];
        mx = fmaxf(mx, d[k]);
    }
    float s = 0.f, m = 0.f;
#pragma unroll
    for (int k = 0; k < 9; k++) {
        float e = __expf(d[k] - mx);
        s += e;
        m += h[k] * e;
    }
    g_mean[idx] = m / s;
}

// ---------------- bw + softmax + xa ----------------
__global__ void k_xa(const float* __restrict__ x, const int* __restrict__ imY,
                     const int* __restrict__ imX) {
    int idx = blockIdx.x * blockDim.x + threadIdx.x;
    if (idx >= 2 * 64 * NP) return;
    int p = idx % NP;
    int c = (idx / NP) & 63;
    int b = idx / (64 * NP);
    int iy = imY[p], ix = imX[p];
    const float* xbc = x + (b * 64 + c) * (HIN * HIN);
    float h[9];
    gather_h(xbc, iy, ix, h);
    float m = g_mean[idx];
    float sd = g_sigma[(b * 2 + 0) * NP + p];
    float sr = g_sigma[(b * 2 + 1) * NP + p];
    float bw[9], mx = -1e30f;
#pragma unroll
    for (int k = 0; k < 9; k++) {
        float d = g_dw[(c * 9 + k) * NP + p];
        bw[k] = sd * d + sr * fabsf(h[k] - m);
        mx = fmaxf(mx, bw[k]);
    }
    float s = 0.f, acc = 0.f;
#pragma unroll
    for (int k = 0; k < 9; k++) {
        float e = __expf(bw[k] - mx);
        s += e;
        acc += h[k] * e;
    }
    g_xa[idx] = acc / s;
}

// ---------------- per-pixel 64x3 contraction ----------------
__global__ void k_out(float* __restrict__ out) {
    int idx = blockIdx.x * blockDim.x + threadIdx.x;
    if (idx >= 2 * NP) return;
    int p = idx % NP, b = idx / NP;
    float a0 = 0.f, a1 = 0.f, a2 = 0.f;
#pragma unroll 8
    for (int c = 0; c < 64; c++) {
        float v = g_xa[(b * 64 + c) * NP + p];
        a0 += v * g_pw[(c * 3 + 0) * NP + p];
        a1 += v * g_pw[(c * 3 + 1) * NP + p];
        a2 += v * g_pw[(c * 3 + 2) * NP + p];
    }
    out[(b * 3 + 0) * NP + p] = a0;
    out[(b * 3 + 1) * NP + p] = a1;
    out[(b * 3 + 2) * NP + p] = a2;
}

// ---------------- launch ----------------
extern "C" void kernel_launch(void* const* d_in, const int* in_sizes, int n_in,
                              void* d_out, int out_size) {
    const float* x      = (const float*)d_in[0];
    const float* pose   = (const float*)d_in[1];
    const int*   imY    = (const int*)d_in[2];
    const int*   imX    = (const int*)d_in[3];
    const float* sig_w1 = (const float*)d_in[4];
    const float* sig_b1 = (const float*)d_in[5];
    const float* sig_w2 = (const float*)d_in[6];
    const float* sig_b2 = (const float*)d_in[7];
    const float* sig_w3 = (const float*)d_in[8];
    const float* sig_b3 = (const float*)d_in[9];
    const float* dw_w1  = (const float*)d_in[10];
    const float* dw_b1  = (const float*)d_in[11];
    const float* dw_w2  = (const float*)d_in[12];
    const float* dw_b2  = (const float*)d_in[13];
    const float* dw_w3  = (const float*)d_in[14];
    const float* dw_b3  = (const float*)d_in[15];
    const float* pw_w1  = (const float*)d_in[16];
    const float* pw_b1  = (const float*)d_in[17];
    const float* pw_w2  = (const float*)d_in[18];
    const float* pw_b2  = (const float*)d_in[19];
    const float* pw_w3  = (const float*)d_in[20];
    const float* pw_b3  = (const float*)d_in[21];

    const int NT64 = NP / 64;    // 576
    const int NTC  = NP / 128;   // 288

    // ===== dw chain: 3 -> 64 -> 256 -> 576 =====
    k_gemm1x1<-1, BUF_A, true><<<dim3(NT64, 1), 256>>>(dw_w1, dw_b1, pose, 3);
    k_gemm_mma<BUF_A, BUF_B, true ><<<dim3(NTC, 2), 256>>>(dw_w2, dw_b2, 256, 64);
    k_gemm_mma<BUF_B, BUF_DW, false><<<dim3(NTC, 5), 256>>>(dw_w3, dw_b3, 576, 256);

    // ===== pw chain: 3 -> 64 -> 256 -> 192 =====
    k_gemm1x1<-1, BUF_A, true><<<dim3(NT64, 1), 256>>>(pw_w1, pw_b1, pose, 3);
    k_gemm_mma<BUF_A, BUF_B, true ><<<dim3(NTC, 2), 256>>>(pw_w2, pw_b2, 256, 64);
    k_gemm_mma<BUF_B, BUF_PW, false><<<dim3(NTC, 2), 256>>>(pw_w3, pw_b3, 192, 256);

    // gather + softmax(dw)-weighted mean
    k_mean<<<(2 * 64 * NP) / 256, 256>>>(x, imY, imX);

    // sigma net: 3x3 convs, pad 1 (16x32 tiles, 2 px/thread)
    k_conv3x3<BUF_MEAN, BUF_S1, true ><<<dim3(12, 6, 2 * 4), dim3(16, 16)>>>(sig_w1, sig_b1, 64, 64);
    k_conv3x3<BUF_S1, BUF_S2, true ><<<dim3(12, 6, 2 * 4), dim3(16, 16)>>>(sig_w2, sig_b2, 64, 64);
    k_conv3x3<BUF_S2, BUF_SIGMA, false><<<dim3(12, 6, 2 * 1), dim3(16, 16)>>>(sig_w3, sig_b3, 64, 2);

    // bw + softmax + xa
    k_xa<<<(2 * 64 * NP) / 256, 256>>>(x, imY, imX);

    // out[b,o,p] = sum_c xa[b,c,p] * pw[c,o,p]
    k_out<<<(2 * NP + 255) / 256, 256>>>((float*)d_out);
}

// round 13
// speedup vs baseline: 2.2917x; 1.3556x over previous
#include <cuda_runtime.h>
#include <math.h>
#include <stdint.h>

#define NP 36864          // 192*192 output pixels
#define WOUT 192
#define HIN 96

// ---------------- static scratch (no allocations allowed) ----------------
__device__ float g_a[64 * NP];
__device__ float g_b[256 * NP];
__device__ float g_dw[576 * NP];
__device__ float g_pw[192 * NP];
__device__ float g_mean[2 * 64 * NP];
__device__ float g_s1[2 * 64 * NP];
__device__ float g_s2[2 * 64 * NP];
__device__ float g_sigma[2 * 2 * NP];
__device__ float g_xa[2 * 64 * NP];

#define BUF_A     0
#define BUF_B     1
#define BUF_DW    2
#define BUF_PW    3
#define BUF_MEAN  4
#define BUF_S1    5
#define BUF_S2    6
#define BUF_SIGMA 7
#define BUF_XA    8

__device__ __forceinline__ float* buf_ptr(int sel) {
    switch (sel) {
        case BUF_A:     return g_a;
        case BUF_B:     return g_b;
        case BUF_DW:    return g_dw;
        case BUF_PW:    return g_pw;
        case BUF_MEAN:  return g_mean;
        case BUF_S1:    return g_s1;
        case BUF_S2:    return g_s2;
        case BUF_SIGMA: return g_sigma;
        default:        return g_xa;
    }
}

// ---------------- tf32 helpers (compute_80+ portable) --------------------
__device__ __forceinline__ float to_tf32(float x) {
    uint32_t o;
    asm("cvt.rna.tf32.f32 %0, %1;" : "=r"(o) : "f"(x));
    return __uint_as_float(o);
}
__device__ __forceinline__ void mma_tf32(float* d, const uint32_t* a, const uint32_t* b) {
    asm volatile(
        "mma.sync.aligned.m16n8k8.row.col.f32.tf32.tf32.f32 "
        "{%0,%1,%2,%3}, {%4,%5,%6,%7}, {%8,%9}, {%0,%1,%2,%3};"
        : "+f"(d[0]), "+f"(d[1]), "+f"(d[2]), "+f"(d[3])
        : "r"(a[0]), "r"(a[1]), "r"(a[2]), "r"(a[3]), "r"(b[0]), "r"(b[1]));
}

// ---------------- 1x1 conv as tf32 tensor-core GEMM ----------------
// Block tile 128(m) x 128(n), K-chunks of 32; 8 warps, warp tile 64x32.
template<int SRC, int DST, bool RELU>
__global__ void __launch_bounds__(256)
k_gemm_mma(const float* __restrict__ W, const float* __restrict__ bias,
           int OC, int IC) {
    const float* __restrict__ X = buf_ptr(SRC);
    float* __restrict__ Y = buf_ptr(DST);

    __shared__ __align__(16) float sA[128 * 36];   // [m][k]
    __shared__ __align__(16) float sB[32 * 136];   // [k][n]

    const int tid  = threadIdx.x;
    const int lane = tid & 31, wid = tid >> 5;
    const int m0 = blockIdx.y * 128, n0 = blockIdx.x * 128;
    const int wm = (wid & 1) * 64;
    const int wn = (wid >> 1) * 32;

    float acc[4][4][4];
#pragma unroll
    for (int i = 0; i < 4; i++)
#pragma unroll
        for (int j = 0; j < 4; j++)
#pragma unroll
            for (int r = 0; r < 4; r++) acc[i][j][r] = 0.f;

    const int nch = IC >> 5;
    for (int t = 0; t < nch; t++) {
        const int k0 = t * 32;
#pragma unroll
        for (int i = 0; i < 4; i++) {
            int e = tid + i * 256;
            int r = e >> 3, c = e & 7;
            float4 v = make_float4(0.f, 0.f, 0.f, 0.f);
            if (m0 + r < OC)
                v = *reinterpret_cast<const float4*>(W + (size_t)(m0 + r) * IC + k0 + c * 4);
            v.x = to_tf32(v.x); v.y = to_tf32(v.y);
            v.z = to_tf32(v.z); v.w = to_tf32(v.w);
            *reinterpret_cast<float4*>(sA + r * 36 + c * 4) = v;
        }
#pragma unroll
        for (int i = 0; i < 4; i++) {
            int e = tid + i * 256;
            int r = e >> 5, c = e & 31;
            float4 v = *reinterpret_cast<const float4*>(X + (size_t)(k0 + r) * NP + n0 + c * 4);
            v.x = to_tf32(v.x); v.y = to_tf32(v.y);
            v.z = to_tf32(v.z); v.w = to_tf32(v.w);
            *reinterpret_cast<float4*>(sB + r * 136 + c * 4) = v;
        }
        __syncthreads();
#pragma unroll
        for (int ks = 0; ks < 4; ks++) {
            const int kk = ks * 8;
            uint32_t a[4][4], b[4][2];
#pragma unroll
            for (int i = 0; i < 4; i++) {
                const float* base = sA + (wm + i * 16 + (lane >> 2)) * 36 + kk + (lane & 3);
                a[i][0] = __float_as_uint(base[0]);
                a[i][1] = __float_as_uint(base[8 * 36]);
                a[i][2] = __float_as_uint(base[4]);
                a[i][3] = __float_as_uint(base[8 * 36 + 4]);
            }
#pragma unroll
            for (int j = 0; j < 4; j++) {
                const float* base = sB + (kk + (lane & 3)) * 136 + wn + j * 8 + (lane >> 2);
                b[j][0] = __float_as_uint(base[0]);
                b[j][1] = __float_as_uint(base[4 * 136]);
            }
#pragma unroll
            for (int i = 0; i < 4; i++)
#pragma unroll
                for (int j = 0; j < 4; j++)
                    mma_tf32(acc[i][j], a[i], b[j]);
        }
        __syncthreads();
    }

#pragma unroll
    for (int i = 0; i < 4; i++) {
#pragma unroll
        for (int half = 0; half < 2; half++) {
            int oc = m0 + wm + i * 16 + (lane >> 2) + half * 8;
            if (oc < OC) {
                float bb = bias[oc];
#pragma unroll
                for (int j = 0; j < 4; j++) {
                    int col = n0 + wn + j * 8 + (lane & 3) * 2;
                    float v0 = acc[i][j][half * 2 + 0] + bb;
                    float v1 = acc[i][j][half * 2 + 1] + bb;
                    if (RELU) { v0 = fmaxf(v0, 0.f); v1 = fmaxf(v1, 0.f); }
                    *reinterpret_cast<float2*>(Y + (size_t)oc * NP + col) =
                        make_float2(v0, v1);
                }
            }
        }
    }
}

// ---------------- 3x3 conv (64->64) as implicit tf32 GEMM ----------------
// out[b,oc,y,x] = relu(bias[oc] + sum_{ic,ky,kx} W[oc,ic,ky,kx]*in[b,ic,y+ky-1,x+kx-1])
// Block tile: 64 oc x 128 pixel-batch; K loop = 9 taps x 2 ic-chunks of 32.
// 8 warps: 2(m) x 4(n), warp tile 32x32.
template<int SRC, int DST, bool RELU>
__global__ void __launch_bounds__(256)
k_conv_mma(const float* __restrict__ W, const float* __restrict__ bias) {
    const float* __restrict__ in = buf_ptr(SRC);
    float* __restrict__ out = buf_ptr(DST);

    __shared__ __align__(16) float sA[64 * 36];    // [oc][ic-chunk]
    __shared__ __align__(16) float sB[32 * 136];   // [ic][pixel]

    const int tid  = threadIdx.x;
    const int lane = tid & 31, wid = tid >> 5;
    const int q0 = blockIdx.x * 128;          // pixel-batch offset
    const int b  = q0 / NP;
    const int p0 = q0 - b * NP;
    const float* __restrict__ inb = in + (size_t)b * 64 * NP;
    const int wm = (wid & 1) * 32;
    const int wn = (wid >> 1) * 32;

    float acc[2][4][4];
#pragma unroll
    for (int i = 0; i < 2; i++)
#pragma unroll
        for (int j = 0; j < 4; j++)
#pragma unroll
            for (int r = 0; r < 4; r++) acc[i][j][r] = 0.f;

    for (int tap = 0; tap < 9; tap++) {
        const int ky = tap / 3, kx = tap - ky * 3;
        const int off = (ky - 1) * WOUT + (kx - 1);
#pragma unroll
        for (int icc = 0; icc < 2; icc++) {
            const int ic0 = icc * 32;
            // A tile: 64 oc x 32 ic (OIHW, stride 9 per ic)
#pragma unroll
            for (int i = 0; i < 8; i++) {
                int e = tid + i * 256;
                int r = e >> 5, c = e & 31;
                sA[r * 36 + c] = to_tf32(W[((size_t)r * 64 + ic0 + c) * 9 + tap]);
            }
            // B tile: 32 ic x 128 pixels (shifted with boundary mask)
#pragma unroll
            for (int i = 0; i < 16; i++) {
                int e = tid + i * 256;
                int r = e >> 7, c = e & 127;
                int p = p0 + c;
                int y = p / WOUT, x = p - y * WOUT;
                int gy = y + ky - 1, gx = x + kx - 1;
                float v = 0.f;
                if (gy >= 0 && gy < WOUT && gx >= 0 && gx < WOUT)
                    v = inb[(size_t)(ic0 + r) * NP + p + off];
                sB[r * 136 + c] = to_tf32(v);
            }
            __syncthreads();
#pragma unroll
            for (int ks = 0; ks < 4; ks++) {
                const int kk = ks * 8;
                uint32_t a[2][4], bf[4][2];
#pragma unroll
                for (int i = 0; i < 2; i++) {
                    const float* base = sA + (wm + i * 16 + (lane >> 2)) * 36 + kk + (lane & 3);
                    a[i][0] = __float_as_uint(base[0]);
                    a[i][1] = __float_as_uint(base[8 * 36]);
                    a[i][2] = __float_as_uint(base[4]);
                    a[i][3] = __float_as_uint(base[8 * 36 + 4]);
                }
#pragma unroll
                for (int j = 0; j < 4; j++) {
                    const float* base = sB + (kk + (lane & 3)) * 136 + wn + j * 8 + (lane >> 2);
                    bf[j][0] = __float_as_uint(base[0]);
                    bf[j][1] = __float_as_uint(base[4 * 136]);
                }
#pragma unroll
                for (int i = 0; i < 2; i++)
#pragma unroll
                    for (int j = 0; j < 4; j++)
                        mma_tf32(acc[i][j], a[i], bf[j]);
            }
            __syncthreads();
        }
    }

#pragma unroll
    for (int i = 0; i < 2; i++) {
#pragma unroll
        for (int half = 0; half < 2; half++) {
            int oc = wm + i * 16 + (lane >> 2) + half * 8;
            float bb = bias[oc];
#pragma unroll
            for (int j = 0; j < 4; j++) {
                int col = wn + j * 8 + (lane & 3) * 2;
                float v0 = acc[i][j][half * 2 + 0] + bb;
                float v1 = acc[i][j][half * 2 + 1] + bb;
                if (RELU) { v0 = fmaxf(v0, 0.f); v1 = fmaxf(v1, 0.f); }
                *reinterpret_cast<float2*>(out + (size_t)(b * 64 + oc) * NP + p0 + col) =
                    make_float2(v0, v1);
            }
        }
    }
}

// ---------------- small fp32 GEMM for layer 1 (IC=3) ----------------
template<int SRC, int DST, bool RELU>
__global__ void k_gemm1x1(const float* __restrict__ W, const float* __restrict__ bias,
                          const float* __restrict__ Xext, int IC) {
    const float* __restrict__ X = (SRC < 0) ? Xext : buf_ptr(SRC);
    float* __restrict__ Y = buf_ptr(DST);

    __shared__ float As[16][65];
    __shared__ float Bs[16][64];
    const int tid = threadIdx.x;
    const int tx = tid & 15, ty = tid >> 4;
    const int m0 = blockIdx.y * 64;
    const int n0 = blockIdx.x * 64;

    float acc[4][4];
#pragma unroll
    for (int i = 0; i < 4; i++)
#pragma unroll
        for (int j = 0; j < 4; j++) acc[i][j] = 0.f;

    for (int k0 = 0; k0 < IC; k0 += 16) {
#pragma unroll
        for (int i = 0; i < 4; i++) {
            int e = tid + i * 256;
            int k = e & 15, m = e >> 4;
            As[k][m] = (k0 + k < IC) ? W[(m0 + m) * IC + k0 + k] : 0.f;
        }
#pragma unroll
        for (int i = 0; i < 4; i++) {
            int e = tid + i * 256;
            int n = e & 63, k = e >> 6;
            Bs[k][n] = (k0 + k < IC) ? X[(k0 + k) * NP + n0 + n] : 0.f;
        }
        __syncthreads();
#pragma unroll
        for (int k = 0; k < 16; k++) {
            float a[4], b[4];
#pragma unroll
            for (int i = 0; i < 4; i++) a[i] = As[k][ty * 4 + i];
#pragma unroll
            for (int j = 0; j < 4; j++) b[j] = Bs[k][tx * 4 + j];
#pragma unroll
            for (int i = 0; i < 4; i++)
#pragma unroll
                for (int j = 0; j < 4; j++) acc[i][j] += a[i] * b[j];
        }
        __syncthreads();
    }
#pragma unroll
    for (int i = 0; i < 4; i++) {
        float bb = bias[m0 + ty * 4 + i];
#pragma unroll
        for (int j = 0; j < 4; j++) {
            float v = acc[i][j] + bb;
            if (RELU) v = fmaxf(v, 0.f);
            Y[(m0 + ty * 4 + i) * NP + n0 + tx * 4 + j] = v;
        }
    }
}

// ---------------- direct 3x3 conv, pad 1 (layer 3: 64->2) ----------------
template<int SRC, int DST, bool RELU>
__global__ void k_conv3x3(const float* __restrict__ W, const float* __restrict__ bias,
                          int IC, int OC) {
    const float* __restrict__ in = buf_ptr(SRC);
    float* __restrict__ out = buf_ptr(DST);

    __shared__ float s_in[8][34][18];
    __shared__ float s_w[8][16][9];
    const int tx = threadIdx.x, ty = threadIdx.y;
    const int tid = ty * 16 + tx;
    const int x0 = blockIdx.x * 16, y0 = blockIdx.y * 32;
    const int noct = (OC + 15) / 16;
    const int b = blockIdx.z / noct;
    const int oc0 = (blockIdx.z % noct) * 16;

    float acc[16][2];
#pragma unroll
    for (int o = 0; o < 16; o++) { acc[o][0] = 0.f; acc[o][1] = 0.f; }

    for (int ic0 = 0; ic0 < IC; ic0 += 8) {
        for (int i = tid; i < 8 * 34 * 18; i += 256) {
            int ic = i / 612;
            int r = i - ic * 612;
            int yy = r / 18, xx = r - yy * 18;
            int gy = y0 + yy - 1, gx = x0 + xx - 1;
            float v = 0.f;
            if (gy >= 0 && gy < WOUT && gx >= 0 && gx < WOUT)
                v = in[((b * IC + ic0 + ic) * WOUT + gy) * WOUT + gx];
            s_in[ic][yy][xx] = v;
        }
        for (int i = tid; i < 8 * 16 * 9; i += 256) {
            int o = i / 72;
            int r = i - o * 72;
            int ic = r / 9, j = r - ic * 9;
            float v = 0.f;
            if (oc0 + o < OC) v = W[((oc0 + o) * IC + ic0 + ic) * 9 + j];
            s_w[ic][o][j] = v;
        }
        __syncthreads();
#pragma unroll 2
        for (int ic = 0; ic < 8; ic++) {
            float v[4][3];
#pragma unroll
            for (int r = 0; r < 4; r++)
#pragma unroll
                for (int c = 0; c < 3; c++)
                    v[r][c] = s_in[ic][ty * 2 + r][tx + c];
#pragma unroll
            for (int o = 0; o < 16; o++) {
#pragma unroll
                for (int ky = 0; ky < 3; ky++)
#pragma unroll
                    for (int kx = 0; kx < 3; kx++) {
                        float ww = s_w[ic][o][ky * 3 + kx];
                        acc[o][0] += ww * v[ky][kx];
                        acc[o][1] += ww * v[ky + 1][kx];
                    }
            }
        }
        __syncthreads();
    }
#pragma unroll
    for (int o = 0; o < 16; o++) {
        if (oc0 + o < OC) {
            float bb = bias[oc0 + o];
            float* dst = out + ((size_t)(b * OC + oc0 + o) * WOUT + y0 + ty * 2) * WOUT
                         + x0 + tx;
#pragma unroll
            for (int dy = 0; dy < 2; dy++) {
                float v = acc[o][dy] + bb;
                if (RELU) v = fmaxf(v, 0.f);
                dst[dy * WOUT] = v;
            }
        }
    }
}

// ---------------- gather helper ----------------
__device__ __forceinline__ void gather_h(const float* __restrict__ xbc, int iy, int ix,
                                         float* h) {
#pragma unroll
    for (int dy = 0; dy < 3; dy++)
#pragma unroll
        for (int dx = 0; dx < 3; dx++) {
            int yy = iy + dy - 1, xx = ix + dx - 1;
            h[dy * 3 + dx] =
                (yy >= 0 && yy < HIN && xx >= 0 && xx < HIN) ? xbc[yy * HIN + xx] : 0.f;
        }
}

// ---------------- gather + softmax(dw) mean ----------------
__global__ void k_mean(const float* __restrict__ x, const int* __restrict__ imY,
                       const int* __restrict__ imX) {
    int idx = blockIdx.x * blockDim.x + threadIdx.x;
    if (idx >= 2 * 64 * NP) return;
    int p = idx % NP;
    int c = (idx / NP) & 63;
    int b = idx / (64 * NP);
    int iy = imY[p], ix = imX[p];
    const float* xbc = x + (b * 64 + c) * (HIN * HIN);
    float h[9];
    gather_h(xbc, iy, ix, h);
    float d[9], mx = -1e30f;
#pragma unroll
    for (int k = 0; k < 9; k++) {
        d[k] = g_dw[(c * 9 + k) * NP + p];
        mx = fmaxf(mx, d[k]);
    }
    float s = 0.f, m = 0.f;
#pragma unroll
    for (int k = 0; k < 9; k++) {
        float e = __expf(d[k] - mx);
        s += e;
        m += h[k] * e;
    }
    g_mean[idx] = m / s;
}

// ---------------- bw + softmax + xa ----------------
__global__ void k_xa(const float* __restrict__ x, const int* __restrict__ imY,
                     const int* __restrict__ imX) {
    int idx = blockIdx.x * blockDim.x + threadIdx.x;
    if (idx >= 2 * 64 * NP) return;
    int p = idx % NP;
    int c = (idx / NP) & 63;
    int b = idx / (64 * NP);
    int iy = imY[p], ix = imX[p];
    const float* xbc = x + (b * 64 + c) * (HIN * HIN);
    float h[9];
    gather_h(xbc, iy, ix, h);
    float m = g_mean[idx];
    float sd = g_sigma[(b * 2 + 0) * NP + p];
    float sr = g_sigma[(b * 2 + 1) * NP + p];
    float bw[9], mx = -1e30f;
#pragma unroll
    for (int k = 0; k < 9; k++) {
        float d = g_dw[(c * 9 + k) * NP + p];
        bw[k] = sd * d + sr * fabsf(h[k] - m);
        mx = fmaxf(mx, bw[k]);
    }
    float s = 0.f, acc = 0.f;
#pragma unroll
    for (int k = 0; k < 9; k++) {
        float e = __expf(bw[k] - mx);
        s += e;
        acc += h[k] * e;
    }
    g_xa[idx] = acc / s;
}

// ---------------- per-pixel 64x3 contraction ----------------
__global__ void k_out(float* __restrict__ out) {
    int idx = blockIdx.x * blockDim.x + threadIdx.x;
    if (idx >= 2 * NP) return;
    int p = idx % NP, b = idx / NP;
    float a0 = 0.f, a1 = 0.f, a2 = 0.f;
#pragma unroll 8
    for (int c = 0; c < 64; c++) {
        float v = g_xa[(b * 64 + c) * NP + p];
        a0 += v * g_pw[(c * 3 + 0) * NP + p];
        a1 += v * g_pw[(c * 3 + 1) * NP + p];
        a2 += v * g_pw[(c * 3 + 2) * NP + p];
    }
    out[(b * 3 + 0) * NP + p] = a0;
    out[(b * 3 + 1) * NP + p] = a1;
    out[(b * 3 + 2) * NP + p] = a2;
}

// ---------------- launch ----------------
extern "C" void kernel_launch(void* const* d_in, const int* in_sizes, int n_in,
                              void* d_out, int out_size) {
    const float* x      = (const float*)d_in[0];
    const float* pose   = (const float*)d_in[1];
    const int*   imY    = (const int*)d_in[2];
    const int*   imX    = (const int*)d_in[3];
    const float* sig_w1 = (const float*)d_in[4];
    const float* sig_b1 = (const float*)d_in[5];
    const float* sig_w2 = (const float*)d_in[6];
    const float* sig_b2 = (const float*)d_in[7];
    const float* sig_w3 = (const float*)d_in[8];
    const float* sig_b3 = (const float*)d_in[9];
    const float* dw_w1  = (const float*)d_in[10];
    const float* dw_b1  = (const float*)d_in[11];
    const float* dw_w2  = (const float*)d_in[12];
    const float* dw_b2  = (const float*)d_in[13];
    const float* dw_w3  = (const float*)d_in[14];
    const float* dw_b3  = (const float*)d_in[15];
    const float* pw_w1  = (const float*)d_in[16];
    const float* pw_b1  = (const float*)d_in[17];
    const float* pw_w2  = (const float*)d_in[18];
    const float* pw_b2  = (const float*)d_in[19];
    const float* pw_w3  = (const float*)d_in[20];
    const float* pw_b3  = (const float*)d_in[21];

    const int NT64 = NP / 64;    // 576
    const int NTC  = NP / 128;   // 288

    // ===== dw chain: 3 -> 64 -> 256 -> 576 =====
    k_gemm1x1<-1, BUF_A, true><<<dim3(NT64, 1), 256>>>(dw_w1, dw_b1, pose, 3);
    k_gemm_mma<BUF_A, BUF_B, true ><<<dim3(NTC, 2), 256>>>(dw_w2, dw_b2, 256, 64);
    k_gemm_mma<BUF_B, BUF_DW, false><<<dim3(NTC, 5), 256>>>(dw_w3, dw_b3, 576, 256);

    // ===== pw chain: 3 -> 64 -> 256 -> 192 =====
    k_gemm1x1<-1, BUF_A, true><<<dim3(NT64, 1), 256>>>(pw_w1, pw_b1, pose, 3);
    k_gemm_mma<BUF_A, BUF_B, true ><<<dim3(NTC, 2), 256>>>(pw_w2, pw_b2, 256, 64);
    k_gemm_mma<BUF_B, BUF_PW, false><<<dim3(NTC, 2), 256>>>(pw_w3, pw_b3, 192, 256);

    // gather + softmax(dw)-weighted mean
    k_mean<<<(2 * 64 * NP) / 256, 256>>>(x, imY, imX);

    // sigma net: layers 1&2 as implicit tf32 GEMM conv, layer 3 direct fp32
    k_conv_mma<BUF_MEAN, BUF_S1, true><<<2 * NP / 128, 256>>>(sig_w1, sig_b1);
    k_conv_mma<BUF_S1, BUF_S2, true><<<2 * NP / 128, 256>>>(sig_w2, sig_b2);
    k_conv3x3<BUF_S2, BUF_SIGMA, false><<<dim3(12, 6, 2 * 1), dim3(16, 16)>>>(sig_w3, sig_b3, 64, 2);

    // bw + softmax + xa
    k_xa<<<(2 * 64 * NP) / 256, 256>>>(x, imY, imX);

    // out[b,o,p] = sum_c xa[b,c,p] * pw[c,o,p]
    k_out<<<(2 * NP + 255) / 256, 256>>>((float*)d_out);
}

// round 15
// speedup vs baseline: 2.5595x; 1.1168x over previous
#include <cuda_runtime.h>
#include <math.h>
#include <stdint.h>

#define NP 36864          // 192*192 output pixels
#define WOUT 192
#define HIN 96

// ---------------- static scratch (no allocations allowed) ----------------
__device__ float g_a[64 * NP];
__device__ float g_b[256 * NP];
__device__ float g_dw[576 * NP];
__device__ float g_pw[192 * NP];
__device__ float g_mean[2 * 64 * NP];
__device__ float g_s1[2 * 64 * NP];
__device__ float g_s2[2 * 64 * NP];
__device__ float g_sigma[2 * 2 * NP];
__device__ float g_xa[2 * 64 * NP];
__device__ float g_wr[303104];          // tf32-rounded weights arena

// arena offsets
#define WOFF_DW2  0         // 256*64   = 16384
#define WOFF_DW3  16384     // 576*256  = 147456
#define WOFF_PW2  163840    // 256*64   = 16384
#define WOFF_PW3  180224    // 192*256  = 49152
#define WOFF_SIG1 229376    // 64*64*9  = 36864
#define WOFF_SIG2 266240    // 64*64*9  = 36864  -> end 303104

#define BUF_A     0
#define BUF_B     1
#define BUF_DW    2
#define BUF_PW    3
#define BUF_MEAN  4
#define BUF_S1    5
#define BUF_S2    6
#define BUF_SIGMA 7
#define BUF_XA    8

__device__ __forceinline__ float* buf_ptr(int sel) {
    switch (sel) {
        case BUF_A:     return g_a;
        case BUF_B:     return g_b;
        case BUF_DW:    return g_dw;
        case BUF_PW:    return g_pw;
        case BUF_MEAN:  return g_mean;
        case BUF_S1:    return g_s1;
        case BUF_S2:    return g_s2;
        case BUF_SIGMA: return g_sigma;
        default:        return g_xa;
    }
}

// ---------------- tf32 / mma / cp.async helpers (compute_80+ portable) ----
__device__ __forceinline__ float to_tf32(float x) {
    uint32_t o;
    asm("cvt.rna.tf32.f32 %0, %1;" : "=r"(o) : "f"(x));
    return __uint_as_float(o);
}
__device__ __forceinline__ void mma_tf32(float* d, const uint32_t* a, const uint32_t* b) {
    asm volatile(
        "mma.sync.aligned.m16n8k8.row.col.f32.tf32.tf32.f32 "
        "{%0,%1,%2,%3}, {%4,%5,%6,%7}, {%8,%9}, {%0,%1,%2,%3};"
        : "+f"(d[0]), "+f"(d[1]), "+f"(d[2]), "+f"(d[3])
        : "r"(a[0]), "r"(a[1]), "r"(a[2]), "r"(a[3]), "r"(b[0]), "r"(b[1]));
}
__device__ __forceinline__ void cp16(float* dst_smem, const float* src, bool pred) {
    uint32_t d = (uint32_t)__cvta_generic_to_shared(dst_smem);
    int sz = pred ? 16 : 0;
    asm volatile("cp.async.cg.shared.global [%0], [%1], 16, %2;"
                 :: "r"(d), "l"(src), "r"(sz));
}
__device__ __forceinline__ void cp4(float* dst_smem, const float* src, bool pred) {
    uint32_t d = (uint32_t)__cvta_generic_to_shared(dst_smem);
    int sz = pred ? 4 : 0;
    asm volatile("cp.async.ca.shared.global [%0], [%1], 4, %2;"
                 :: "r"(d), "l"(src), "r"(sz));
}
#define CP_COMMIT() asm volatile("cp.async.commit_group;" ::: "memory")
template<int N> __device__ __forceinline__ void cp_wait() {
    asm volatile("cp.async.wait_group %0;" :: "n"(N) : "memory");
}

// ---------------- weight pre-rounding ----------------
__global__ void k_round(const float* __restrict__ src, int off, int n) {
    int i = blockIdx.x * 256 + threadIdx.x;
    if (i < n) g_wr[off + i] = to_tf32(src[i]);
}

// ---------------- 1x1 conv as tf32 GEMM, cp.async depth-2 pipeline -------
// Block tile 128(m) x 128(n), BK=16; 8 warps, warp tile 64x32.
// Weights come pre-rounded from g_wr; X activations pre-rounded by producer.
template<int SRC, int DST, bool RELU, bool ROUND>
__global__ void __launch_bounds__(256)
k_gemm_mma(int woff, const float* __restrict__ bias, int OC, int IC) {
    const float* __restrict__ W = g_wr + woff;
    const float* __restrict__ X = buf_ptr(SRC);
    float* __restrict__ Y = buf_ptr(DST);

    __shared__ __align__(16) float sA[2][128 * 20];   // [m][k], pitch 20
    __shared__ __align__(16) float sB[2][16 * 136];   // [k][n], pitch 136

    const int tid  = threadIdx.x;
    const int lane = tid & 31, wid = tid >> 5;
    const int m0 = blockIdx.y * 128, n0 = blockIdx.x * 128;
    const int wm = (wid & 1) * 64;
    const int wn = (wid >> 1) * 32;
    const int nch = IC >> 4;

    float acc[4][4][4];
#pragma unroll
    for (int i = 0; i < 4; i++)
#pragma unroll
        for (int j = 0; j < 4; j++)
#pragma unroll
            for (int r = 0; r < 4; r++) acc[i][j][r] = 0.f;

    auto issue = [&](int t) {
        float* dA = sA[t & 1];
        float* dB = sB[t & 1];
        const int k0 = t * 16;
#pragma unroll
        for (int i = 0; i < 2; i++) {
            int e = tid + i * 256;
            int r = e >> 2, c = e & 3;
            cp16(dA + r * 20 + c * 4, W + (size_t)(m0 + r) * IC + k0 + c * 4,
                 m0 + r < OC);
        }
#pragma unroll
        for (int i = 0; i < 2; i++) {
            int e = tid + i * 256;
            int r = e >> 5, c = e & 31;
            cp16(dB + r * 136 + c * 4, X + (size_t)(k0 + r) * NP + n0 + c * 4, true);
        }
        CP_COMMIT();
    };

    issue(0);
    if (nch > 1) issue(1);

    for (int t = 0; t < nch; t++) {
        if (t < nch - 1) cp_wait<1>(); else cp_wait<0>();
        __syncthreads();
        const float* cA = sA[t & 1];
        const float* cB = sB[t & 1];
#pragma unroll
        for (int ks = 0; ks < 2; ks++) {
            const int kk = ks * 8;
            uint32_t a[4][4], b[4][2];
#pragma unroll
            for (int i = 0; i < 4; i++) {
                const float* base = cA + (wm + i * 16 + (lane >> 2)) * 20 + kk + (lane & 3);
                a[i][0] = __float_as_uint(base[0]);
                a[i][1] = __float_as_uint(base[8 * 20]);
                a[i][2] = __float_as_uint(base[4]);
                a[i][3] = __float_as_uint(base[8 * 20 + 4]);
            }
#pragma unroll
            for (int j = 0; j < 4; j++) {
                const float* base = cB + (kk + (lane & 3)) * 136 + wn + j * 8 + (lane >> 2);
                b[j][0] = __float_as_uint(base[0]);
                b[j][1] = __float_as_uint(base[4 * 136]);
            }
#pragma unroll
            for (int i = 0; i < 4; i++)
#pragma unroll
                for (int j = 0; j < 4; j++)
                    mma_tf32(acc[i][j], a[i], b[j]);
        }
        __syncthreads();
        if (t + 2 < nch) issue(t + 2);
    }

#pragma unroll
    for (int i = 0; i < 4; i++) {
#pragma unroll
        for (int half = 0; half < 2; half++) {
            int oc = m0 + wm + i * 16 + (lane >> 2) + half * 8;
            if (oc < OC) {
                float bb = bias[oc];
#pragma unroll
                for (int j = 0; j < 4; j++) {
                    int col = n0 + wn + j * 8 + (lane & 3) * 2;
                    float v0 = acc[i][j][half * 2 + 0] + bb;
                    float v1 = acc[i][j][half * 2 + 1] + bb;
                    if (RELU) { v0 = fmaxf(v0, 0.f); v1 = fmaxf(v1, 0.f); }
                    if (ROUND) { v0 = to_tf32(v0); v1 = to_tf32(v1); }
                    *reinterpret_cast<float2*>(Y + (size_t)oc * NP + col) =
                        make_float2(v0, v1);
                }
            }
        }
    }
}

// ---------------- 3x3 conv (64->64) implicit GEMM, cp.async pipeline -----
// Block: 64 oc x 128 pixels; 36 stages = 9 taps x 4 ic-chunks of 16.
template<int SRC, int DST, bool RELU, bool ROUND>
__global__ void __launch_bounds__(256)
k_conv_mma(int woff, const float* __restrict__ bias) {
    const float* __restrict__ Wt = g_wr + woff;
    const float* __restrict__ in = buf_ptr(SRC);
    float* __restrict__ out = buf_ptr(DST);

    __shared__ __align__(16) float sA[2][64 * 20];
    __shared__ __align__(16) float sB[2][16 * 136];

    const int tid  = threadIdx.x;
    const int lane = tid & 31, wid = tid >> 5;
    const int q0 = blockIdx.x * 128;
    const int b  = q0 / NP;
    const int p0 = q0 - b * NP;
    const float* __restrict__ inb = in + (size_t)b * 64 * NP;
    const int wm = (wid & 1) * 32;
    const int wn = (wid >> 1) * 32;
    const int NST = 36;

    float acc[2][4][4];
#pragma unroll
    for (int i = 0; i < 2; i++)
#pragma unroll
        for (int j = 0; j < 4; j++)
#pragma unroll
            for (int r = 0; r < 4; r++) acc[i][j][r] = 0.f;

    auto issue = [&](int s) {
        const int tap = s >> 2, icc = (s & 3) * 16;
        const int ky = tap / 3, kx = tap - ky * 3;
        const int off = (ky - 1) * WOUT + (kx - 1);
        float* dA = sA[s & 1];
        float* dB = sB[s & 1];
#pragma unroll
        for (int i = 0; i < 4; i++) {
            int e = tid + i * 256;
            int r = e >> 4, c = e & 15;
            cp4(dA + r * 20 + c, Wt + ((size_t)r * 64 + icc + c) * 9 + tap, true);
        }
#pragma unroll
        for (int i = 0; i < 8; i++) {
            int e = tid + i * 256;
            int r = e >> 7, c = e & 127;
            int p = p0 + c;
            int y = p / WOUT, x = p - y * WOUT;
            int gy = y + ky - 1, gx = x + kx - 1;
            bool ok = (gy >= 0) && (gy < WOUT) && (gx >= 0) && (gx < WOUT);
            cp4(dB + r * 136 + c, inb + (size_t)(icc + r) * NP + p + off, ok);
        }
        CP_COMMIT();
    };

    issue(0);
    issue(1);

    for (int s = 0; s < NST; s++) {
        if (s < NST - 1) cp_wait<1>(); else cp_wait<0>();
        __syncthreads();
        const float* cA = sA[s & 1];
        const float* cB = sB[s & 1];
#pragma unroll
        for (int ks = 0; ks < 2; ks++) {
            const int kk = ks * 8;
            uint32_t a[2][4], bf[4][2];
#pragma unroll
            for (int i = 0; i < 2; i++) {
                const float* base = cA + (wm + i * 16 + (lane >> 2)) * 20 + kk + (lane & 3);
                a[i][0] = __float_as_uint(base[0]);
                a[i][1] = __float_as_uint(base[8 * 20]);
                a[i][2] = __float_as_uint(base[4]);
                a[i][3] = __float_as_uint(base[8 * 20 + 4]);
            }
#pragma unroll
            for (int j = 0; j < 4; j++) {
                const float* base = cB + (kk + (lane & 3)) * 136 + wn + j * 8 + (lane >> 2);
                bf[j][0] = __float_as_uint(base[0]);
                bf[j][1] = __float_as_uint(base[4 * 136]);
            }
#pragma unroll
            for (int i = 0; i < 2; i++)
#pragma unroll
                for (int j = 0; j < 4; j++)
                    mma_tf32(acc[i][j], a[i], bf[j]);
        }
        __syncthreads();
        if (s + 2 < NST) issue(s + 2);
    }

#pragma unroll
    for (int i = 0; i < 2; i++) {
#pragma unroll
        for (int half = 0; half < 2; half++) {
            int oc = wm + i * 16 + (lane >> 2) + half * 8;
            float bb = bias[oc];
#pragma unroll
            for (int j = 0; j < 4; j++) {
                int col = wn + j * 8 + (lane & 3) * 2;
                float v0 = acc[i][j][half * 2 + 0] + bb;
                float v1 = acc[i][j][half * 2 + 1] + bb;
                if (RELU) { v0 = fmaxf(v0, 0.f); v1 = fmaxf(v1, 0.f); }
                if (ROUND) { v0 = to_tf32(v0); v1 = to_tf32(v1); }
                *reinterpret_cast<float2*>(out + (size_t)(b * 64 + oc) * NP + p0 + col) =
                    make_float2(v0, v1);
            }
        }
    }
}

// ---------------- small fp32 GEMM for layer 1 (IC=3) ----------------
template<int SRC, int DST, bool RELU, bool ROUND>
__global__ void k_gemm1x1(const float* __restrict__ W, const float* __restrict__ bias,
                          const float* __restrict__ Xext, int IC) {
    const float* __restrict__ X = (SRC < 0) ? Xext : buf_ptr(SRC);
    float* __restrict__ Y = buf_ptr(DST);

    __shared__ float As[16][65];
    __shared__ float Bs[16][64];
    const int tid = threadIdx.x;
    const int tx = tid & 15, ty = tid >> 4;
    const int m0 = blockIdx.y * 64;
    const int n0 = blockIdx.x * 64;

    float acc[4][4];
#pragma unroll
    for (int i = 0; i < 4; i++)
#pragma unroll
        for (int j = 0; j < 4; j++) acc[i][j] = 0.f;

    for (int k0 = 0; k0 < IC; k0 += 16) {
#pragma unroll
        for (int i = 0; i < 4; i++) {
            int e = tid + i * 256;
            int k = e & 15, m = e >> 4;
            As[k][m] = (k0 + k < IC) ? W[(m0 + m) * IC + k0 + k] : 0.f;
        }
#pragma unroll
        for (int i = 0; i < 4; i++) {
            int e = tid + i * 256;
            int n = e & 63, k = e >> 6;
            Bs[k][n] = (k0 + k < IC) ? X[(k0 + k) * NP + n0 + n] : 0.f;
        }
        __syncthreads();
#pragma unroll
        for (int k = 0; k < 16; k++) {
            float a[4], b[4];
#pragma unroll
            for (int i = 0; i < 4; i++) a[i] = As[k][ty * 4 + i];
#pragma unroll
            for (int j = 0; j < 4; j++) b[j] = Bs[k][tx * 4 + j];
#pragma unroll
            for (int i = 0; i < 4; i++)
#pragma unroll
                for (int j = 0; j < 4; j++) acc[i][j] += a[i] * b[j];
        }
        __syncthreads();
    }
#pragma unroll
    for (int i = 0; i < 4; i++) {
        float bb = bias[m0 + ty * 4 + i];
#pragma unroll
        for (int j = 0; j < 4; j++) {
            float v = acc[i][j] + bb;
            if (RELU) v = fmaxf(v, 0.f);
            if (ROUND) v = to_tf32(v);
            Y[(m0 + ty * 4 + i) * NP + n0 + tx * 4 + j] = v;
        }
    }
}

// ---------------- direct 3x3 conv, pad 1 (layer 3: 64->2) ----------------
template<int SRC, int DST, bool RELU>
__global__ void k_conv3x3(const float* __restrict__ W, const float* __restrict__ bias,
                          int IC, int OC) {
    const float* __restrict__ in = buf_ptr(SRC);
    float* __restrict__ out = buf_ptr(DST);

    __shared__ float s_in[8][34][18];
    __shared__ float s_w[8][16][9];
    const int tx = threadIdx.x, ty = threadIdx.y;
    const int tid = ty * 16 + tx;
    const int x0 = blockIdx.x * 16, y0 = blockIdx.y * 32;
    const int noct = (OC + 15) / 16;
    const int b = blockIdx.z / noct;
    const int oc0 = (blockIdx.z % noct) * 16;

    float acc[16][2];
#pragma unroll
    for (int o = 0; o < 16; o++) { acc[o][0] = 0.f; acc[o][1] = 0.f; }

    for (int ic0 = 0; ic0 < IC; ic0 += 8) {
        for (int i = tid; i < 8 * 34 * 18; i += 256) {
            int ic = i / 612;
            int r = i - ic * 612;
            int yy = r / 18, xx = r - yy * 18;
            int gy = y0 + yy - 1, gx = x0 + xx - 1;
            float v = 0.f;
            if (gy >= 0 && gy < WOUT && gx >= 0 && gx < WOUT)
                v = in[((b * IC + ic0 + ic) * WOUT + gy) * WOUT + gx];
            s_in[ic][yy][xx] = v;
        }
        for (int i = tid; i < 8 * 16 * 9; i += 256) {
            int o = i / 72;
            int r = i - o * 72;
            int ic = r / 9, j = r - ic * 9;
            float v = 0.f;
            if (oc0 + o < OC) v = W[((oc0 + o) * IC + ic0 + ic) * 9 + j];
            s_w[ic][o][j] = v;
        }
        __syncthreads();
#pragma unroll 2
        for (int ic = 0; ic < 8; ic++) {
            float v[4][3];
#pragma unroll
            for (int r = 0; r < 4; r++)
#pragma unroll
                for (int c = 0; c < 3; c++)
                    v[r][c] = s_in[ic][ty * 2 + r][tx + c];
#pragma unroll
            for (int o = 0; o < 16; o++) {
#pragma unroll
                for (int ky = 0; ky < 3; ky++)
#pragma unroll
                    for (int kx = 0; kx < 3; kx++) {
                        float ww = s_w[ic][o][ky * 3 + kx];
                        acc[o][0] += ww * v[ky][kx];
                        acc[o][1] += ww * v[ky + 1][kx];
                    }
            }
        }
        __syncthreads();
    }
#pragma unroll
    for (int o = 0; o < 16; o++) {
        if (oc0 + o < OC) {
            float bb = bias[oc0 + o];
            float* dst = out + ((size_t)(b * OC + oc0 + o) * WOUT + y0 + ty * 2) * WOUT
                         + x0 + tx;
#pragma unroll
            for (int dy = 0; dy < 2; dy++) {
                float v = acc[o][dy] + bb;
                if (RELU) v = fmaxf(v, 0.f);
                dst[dy * WOUT] = v;
            }
        }
    }
}

// ---------------- gather helper ----------------
__device__ __forceinline__ void gather_h(const float* __restrict__ xbc, int iy, int ix,
                                         float* h) {
#pragma unroll
    for (int dy = 0; dy < 3; dy++)
#pragma unroll
        for (int dx = 0; dx < 3; dx++) {
            int yy = iy + dy - 1, xx = ix + dx - 1;
            h[dy * 3 + dx] =
                (yy >= 0 && yy < HIN && xx >= 0 && xx < HIN) ? xbc[yy * HIN + xx] : 0.f;
        }
}

// ---------------- gather + softmax(dw) mean (tf32-rounded output) --------
__global__ void k_mean(const float* __restrict__ x, const int* __restrict__ imY,
                       const int* __restrict__ imX) {
    int idx = blockIdx.x * blockDim.x + threadIdx.x;
    if (idx >= 2 * 64 * NP) return;
    int p = idx % NP;
    int c = (idx / NP) & 63;
    int b = idx / (64 * NP);
    int iy = imY[p], ix = imX[p];
    const float* xbc = x + (b * 64 + c) * (HIN * HIN);
    float h[9];
    gather_h(xbc, iy, ix, h);
    float d[9], mx = -1e30f;
#pragma unroll
    for (int k = 0; k < 9; k++) {
        d[k] = g_dw[(c * 9 + k) * NP + p];
        mx = fmaxf(mx, d[k]);
    }
    float s = 0.f, m = 0.f;
#pragma unroll
    for (int k = 0; k < 9; k++) {
        float e = __expf(d[k] - mx);
        s += e;
        m += h[k] * e;
    }
    g_mean[idx] = to_tf32(m / s);   // feeds tf32 conv; rounding here keeps MMA unbiased
}

// ---------------- bw + softmax + xa ----------------
__global__ void k_xa(const float* __restrict__ x, const int* __restrict__ imY,
                     const int* __restrict__ imX) {
    int idx = blockIdx.x * blockDim.x + threadIdx.x;
    if (idx >= 2 * 64 * NP) return;
    int p = idx % NP;
    int c = (idx / NP) & 63;
    int b = idx / (64 * NP);
    int iy = imY[p], ix = imX[p];
    const float* xbc = x + (b * 64 + c) * (HIN * HIN);
    float h[9];
    gather_h(xbc, iy, ix, h);
    float m = g_mean[idx];
    float sd = g_sigma[(b * 2 + 0) * NP + p];
    float sr = g_sigma[(b * 2 + 1) * NP + p];
    float bw[9], mx = -1e30f;
#pragma unroll
    for (int k = 0; k < 9; k++) {
        float d = g_dw[(c * 9 + k) * NP + p];
        bw[k] = sd * d + sr * fabsf(h[k] - m);
        mx = fmaxf(mx, bw[k]);
    }
    float s = 0.f, acc = 0.f;
#pragma unroll
    for (int k = 0; k < 9; k++) {
        float e = __expf(bw[k] - mx);
        s += e;
        acc += h[k] * e;
    }
    g_xa[idx] = acc / s;
}

// ---------------- per-pixel 64x3 contraction ----------------
__global__ void k_out(float* __restrict__ out) {
    int idx = blockIdx.x * blockDim.x + threadIdx.x;
    if (idx >= 2 * NP) return;
    int p = idx % NP, b = idx / NP;
    float a0 = 0.f, a1 = 0.f, a2 = 0.f;
#pragma unroll 8
    for (int c = 0; c < 64; c++) {
        float v = g_xa[(b * 64 + c) * NP + p];
        a0 += v * g_pw[(c * 3 + 0) * NP + p];
        a1 += v * g_pw[(c * 3 + 1) * NP + p];
        a2 += v * g_pw[(c * 3 + 2) * NP + p];
    }
    out[(b * 3 + 0) * NP + p] = a0;
    out[(b * 3 + 1) * NP + p] = a1;
    out[(b * 3 + 2) * NP + p] = a2;
}

// ---------------- launch ----------------
extern "C" void kernel_launch(void* const* d_in, const int* in_sizes, int n_in,
                              void* d_out, int out_size) {
    const float* x      = (const float*)d_in[0];
    const float* pose   = (const float*)d_in[1];
    const int*   imY    = (const int*)d_in[2];
    const int*   imX    = (const int*)d_in[3];
    const float* sig_w1 = (const float*)d_in[4];
    const float* sig_b1 = (const float*)d_in[5];
    const float* sig_w2 = (const float*)d_in[6];
    const float* sig_b2 = (const float*)d_in[7];
    const float* sig_w3 = (const float*)d_in[8];
    const float* sig_b3 = (const float*)d_in[9];
    const float* dw_w1  = (const float*)d_in[10];
    const float* dw_b1  = (const float*)d_in[11];
    const float* dw_w2  = (const float*)d_in[12];
    const float* dw_b2  = (const float*)d_in[13];
    const float* dw_w3  = (const float*)d_in[14];
    const float* dw_b3  = (const float*)d_in[15];
    const float* pw_w1  = (const float*)d_in[16];
    const float* pw_b1  = (const float*)d_in[17];
    const float* pw_w2  = (const float*)d_in[18];
    const float* pw_b2  = (const float*)d_in[19];
    const float* pw_w3  = (const float*)d_in[20];
    const float* pw_b3  = (const float*)d_in[21];

    const int NT64 = NP / 64;    // 576
    const int NTC  = NP / 128;   // 288

    // pre-round all tf32-consumed weights into the arena
    k_round<<<(16384 + 255) / 256, 256>>>(dw_w2, WOFF_DW2, 16384);
    k_round<<<(147456 + 255) / 256, 256>>>(dw_w3, WOFF_DW3, 147456);
    k_round<<<(16384 + 255) / 256, 256>>>(pw_w2, WOFF_PW2, 16384);
    k_round<<<(49152 + 255) / 256, 256>>>(pw_w3, WOFF_PW3, 49152);
    k_round<<<(36864 + 255) / 256, 256>>>(sig_w1, WOFF_SIG1, 36864);
    k_round<<<(36864 + 255) / 256, 256>>>(sig_w2, WOFF_SIG2, 36864);

    // ===== dw chain: 3 -> 64 -> 256 -> 576 =====
    k_gemm1x1<-1, BUF_A, true, true><<<dim3(NT64, 1), 256>>>(dw_w1, dw_b1, pose, 3);
    k_gemm_mma<BUF_A, BUF_B, true, true ><<<dim3(NTC, 2), 256>>>(WOFF_DW2, dw_b2, 256, 64);
    k_gemm_mma<BUF_B, BUF_DW, false, false><<<dim3(NTC, 5), 256>>>(WOFF_DW3, dw_b3, 576, 256);

    // ===== pw chain: 3 -> 64 -> 256 -> 192 =====
    k_gemm1x1<-1, BUF_A, true, true><<<dim3(NT64, 1), 256>>>(pw_w1, pw_b1, pose, 3);
    k_gemm_mma<BUF_A, BUF_B, true, true ><<<dim3(NTC, 2), 256>>>(WOFF_PW2, pw_b2, 256, 64);
    k_gemm_mma<BUF_B, BUF_PW, false, false><<<dim3(NTC, 2), 256>>>(WOFF_PW3, pw_b3, 192, 256);

    // gather + softmax(dw)-weighted mean
    k_mean<<<(2 * 64 * NP) / 256, 256>>>(x, imY, imX);

    // sigma net: layers 1&2 implicit tf32 GEMM conv, layer 3 direct fp32
    k_conv_mma<BUF_MEAN, BUF_S1, true, true ><<<2 * NP / 128, 256>>>(WOFF_SIG1, sig_b1);
    k_conv_mma<BUF_S1, BUF_S2, true, false><<<2 * NP / 128, 256>>>(WOFF_SIG2, sig_b2);
    k_conv3x3<BUF_S2, BUF_SIGMA, false><<<dim3(12, 6, 2 * 1), dim3(16, 16)>>>(sig_w3, sig_b3, 64, 2);

    // bw + softmax + xa
    k_xa<<<(2 * 64 * NP) / 256, 256>>>(x, imY, imX);

    // out[b,o,p] = sum_c xa[b,c,p] * pw[c,o,p]
    k_out<<<(2 * NP + 255) / 256, 256>>>((float*)d_out);
}